// round 4
// baseline (speedup 1.0000x reference)
#include <cuda_runtime.h>

#define HH 512
#define WW 1024
#define HWSZ (HH*WW)

// Scratch (device globals; allocation in kernel_launch is forbidden)
__device__ float g_bufA[100 * HWSZ];
__device__ float g_bufB[100 * HWSZ];
__device__ float g_part[21 * 4 * HWSZ];

// ---------------- cp.async helpers ----------------
__device__ __forceinline__ unsigned smem_u32(const void* p) {
    unsigned a;
    asm("{ .reg .u64 t; cvta.to.shared.u64 t, %1; cvt.u32.u64 %0, t; }" : "=r"(a) : "l"(p));
    return a;
}
__device__ __forceinline__ void cpa4(unsigned dst, const void* src, int sz) {
    asm volatile("cp.async.ca.shared.global [%0], [%1], 4, %2;" :: "r"(dst), "l"(src), "r"(sz));
}
__device__ __forceinline__ void cpa_commit() { asm volatile("cp.async.commit_group;"); }
__device__ __forceinline__ void cpa_wait0()  { asm volatile("cp.async.wait_group 0;"); }

// ---------------------------------------------------------------------------
// 3x3 SAME conv: block = 20 oc x (32x16) px, 320 threads, 4oc x 8px / thread.
// cp.async double-buffered staging (10-ic chunks), stride-36 smem rows so the
// inner loop uses LDS.128 (conflict-free for this warp shape).
// smem layout (dynamic): s_in[2][10][18][36], s_w[2][10*9*20]
// ---------------------------------------------------------------------------
#define C3_SIN (2*10*18*36)
#define C3_SW  (2*10*9*20)
#define C3_SMEM ((C3_SIN + C3_SW)*4)

template<int CIN, bool RELU>
__global__ __launch_bounds__(320, 2)
void conv3x3_k(const float* __restrict__ in, const float* __restrict__ w,
               const float* __restrict__ b, float* __restrict__ out)
{
    constexpr int ICC = 10;
    constexpr int OCB = 20;
    constexpr int NCH = CIN / ICC;
    extern __shared__ float sm[];
    float* s_in = sm;              // [2][ICC][18][36]
    float* s_w  = sm + C3_SIN;     // [2][ICC*9*OCB]

    const int tid  = threadIdx.x;
    const int wrp  = tid >> 5;     // 0..9
    const int lane = tid & 31;
    const int ocg  = tid >> 6;     // 0..4
    const int r    = tid & 63;
    const int ty   = r >> 2;       // 0..15
    const int tx   = r & 3;        // 0..3
    const int x0   = blockIdx.x * 32;
    const int y0   = blockIdx.y * 16;
    const int ocb  = blockIdx.z * OCB;

    const unsigned sin_a = smem_u32(s_in);
    const unsigned sw_a  = smem_u32(s_w);

    // stage one 10-ic chunk (input tile + weights) into buffer bufi
    auto stage = [&](int icc, int bufi) {
        const float* inc = in + (size_t)(icc + wrp) * HWSZ;
        unsigned ib = sin_a + (unsigned)(bufi * ICC * 18 * 36 + wrp * 18 * 36) * 4u;
        #pragma unroll
        for (int yy = 0; yy < 18; yy++) {
            const int gy = y0 + yy - 1;
            const bool rowok = (unsigned)gy < HH;
            const float* rp = inc + (size_t)gy * WW;
            {
                const int gx = x0 + lane - 1;
                const bool ok = rowok && (unsigned)gx < WW;
                cpa4(ib + (unsigned)(yy * 36 + lane) * 4u, ok ? (rp + gx) : in, ok ? 4 : 0);
            }
            if (lane < 2) {
                const int gx = x0 + 31 + lane;
                const bool ok = rowok && (unsigned)gx < WW;
                cpa4(ib + (unsigned)(yy * 36 + 32 + lane) * 4u, ok ? (rp + gx) : in, ok ? 4 : 0);
            }
        }
        // weights: warp stages 2 ocs; 90 contiguous gmem floats per oc
        unsigned wb = sw_a + (unsigned)(bufi * ICC * 9 * OCB) * 4u;
        #pragma unroll
        for (int oo = 0; oo < 2; oo++) {
            const int ocl = wrp * 2 + oo;
            const float* wp = w + (size_t)(ocb + ocl) * (CIN * 9) + icc * 9;
            #pragma unroll
            for (int i = 0; i < 3; i++) {
                const int e = lane + i * 32;
                if (e < 90) cpa4(wb + (unsigned)(e * OCB + ocl) * 4u, wp + e, 4);
            }
        }
    };

    float acc[4][8];
    #pragma unroll
    for (int j = 0; j < 4; j++) {
        const float bv = b[ocb + ocg * 4 + j];
        #pragma unroll
        for (int p = 0; p < 8; p++) acc[j][p] = bv;
    }

    stage(0, 0);
    cpa_commit();

    for (int c = 0; c < NCH; c++) {
        cpa_wait0();
        __syncthreads();
        if (c + 1 < NCH) { stage((c + 1) * ICC, (c + 1) & 1); cpa_commit(); }

        const float* bi = s_in + (c & 1) * (ICC * 18 * 36);
        const float* bw = s_w  + (c & 1) * (ICC * 9 * OCB);
        #pragma unroll 2
        for (int ic = 0; ic < ICC; ic++) {
            const float* prow0 = bi + (ic * 18 + ty) * 36 + tx * 8;
            const float* pw    = bw + ic * 9 * OCB + ocg * 4;
            #pragma unroll
            for (int ky = 0; ky < 3; ky++) {
                const float* pr = prow0 + ky * 36;
                const float4 v0 = *(const float4*)pr;
                const float4 v1 = *(const float4*)(pr + 4);
                float rr[10];
                rr[0]=v0.x; rr[1]=v0.y; rr[2]=v0.z; rr[3]=v0.w;
                rr[4]=v1.x; rr[5]=v1.y; rr[6]=v1.z; rr[7]=v1.w;
                rr[8]=pr[8]; rr[9]=pr[9];
                #pragma unroll
                for (int kx = 0; kx < 3; kx++) {
                    const float4 wv = *(const float4*)(pw + (ky * 3 + kx) * OCB);
                    #pragma unroll
                    for (int p = 0; p < 8; p++) {
                        const float iv = rr[p + kx];
                        acc[0][p] = fmaf(wv.x, iv, acc[0][p]);
                        acc[1][p] = fmaf(wv.y, iv, acc[1][p]);
                        acc[2][p] = fmaf(wv.z, iv, acc[2][p]);
                        acc[3][p] = fmaf(wv.w, iv, acc[3][p]);
                    }
                }
            }
        }
    }

    #pragma unroll
    for (int j = 0; j < 4; j++) {
        float* po = out + (size_t)(ocb + ocg * 4 + j) * HWSZ + (y0 + ty) * WW + x0 + tx * 8;
        float v[8];
        #pragma unroll
        for (int p = 0; p < 8; p++) {
            float x = acc[j][p];
            if (RELU) x = (x > 0.f) ? x : 0.01f * x;
            v[p] = x;
        }
        *(float4*)po       = make_float4(v[0], v[1], v[2], v[3]);
        *(float4*)(po + 4) = make_float4(v[4], v[5], v[6], v[7]);
    }
}

// ---------------------------------------------------------------------------
// conv_last (100 -> 441) fused with kernel regression; dy = blockIdx.z.
// Block = 21 oc x (32x8) px, 224 threads (7 warps x 3 oc each).
// Same cp.async double-buffered pipeline, ICC=10.
// smem: s_in[2][10][10][36], s_w[2][10*9*21], s_rgb[3][8][52], s_red[7][8][32][4]
// ---------------------------------------------------------------------------
#define CL_SIN  (2*10*10*36)
#define CL_SW   (2*10*9*21)
#define CL_SRGB (3*8*52)
#define CL_SRED (7*8*32*4)
#define CL_SMEM ((CL_SIN + CL_SW + CL_SRGB + CL_SRED)*4)

__global__ __launch_bounds__(224, 2)
void convlast_k(const float* __restrict__ feat, const float* __restrict__ rgb,
                const float* __restrict__ w, const float* __restrict__ b)
{
    constexpr int ICC = 10;
    constexpr int OCB = 21;
    extern __shared__ float sm[];
    float* s_in  = sm;                          // [2][ICC][10][36]
    float* s_w   = sm + CL_SIN;                 // [2][ICC*9*21]
    float* s_rgb = sm + CL_SIN + CL_SW;         // [3][8][52]
    float* s_red = sm + CL_SIN + CL_SW + CL_SRGB; // [7][8][32][4]

    const int tid  = threadIdx.x;
    const int wrp  = tid >> 5;     // 0..6 (== oc group g)
    const int lane = tid & 31;
    const int g    = wrp;
    const int ty   = lane >> 2;    // 0..7
    const int tx   = lane & 3;     // 0..3
    const int x0   = blockIdx.x * 32;
    const int y0   = blockIdx.y * 8;
    const int z    = blockIdx.z;   // dy
    const int ocb  = z * OCB;

    const unsigned sin_a  = smem_u32(s_in);
    const unsigned sw_a   = smem_u32(s_w);
    const unsigned srgb_a = smem_u32(s_rgb);

    // stage rgb tile once (group 0, waited with chunk 0)
    for (int idx = tid; idx < 3 * 8 * 52; idx += 224) {
        const int xx = idx % 52;
        const int t1 = idx / 52;
        const int yy = t1 % 8;
        const int cc = t1 / 8;
        const int gy = y0 + yy + z - 10;
        const int gx = x0 + xx - 10;
        const bool ok = (unsigned)gy < HH && (unsigned)gx < WW;
        cpa4(srgb_a + (unsigned)idx * 4u,
             ok ? (rgb + (size_t)cc * HWSZ + gy * WW + gx) : rgb, ok ? 4 : 0);
    }

    auto stage = [&](int icc, int bufi) {
        unsigned ib = sin_a + (unsigned)(bufi * ICC * 10 * 36) * 4u;
        for (int rid = wrp; rid < 100; rid += 7) {
            const int ic = rid / 10;
            const int yy = rid - ic * 10;
            const int gy = y0 + yy - 1;
            const bool rowok = (unsigned)gy < HH;
            const float* rp = feat + (size_t)(icc + ic) * HWSZ + (size_t)gy * WW;
            {
                const int gx = x0 + lane - 1;
                const bool ok = rowok && (unsigned)gx < WW;
                cpa4(ib + (unsigned)((ic * 10 + yy) * 36 + lane) * 4u, ok ? (rp + gx) : feat, ok ? 4 : 0);
            }
            if (lane < 2) {
                const int gx = x0 + 31 + lane;
                const bool ok = rowok && (unsigned)gx < WW;
                cpa4(ib + (unsigned)((ic * 10 + yy) * 36 + 32 + lane) * 4u, ok ? (rp + gx) : feat, ok ? 4 : 0);
            }
        }
        unsigned wb = sw_a + (unsigned)(bufi * ICC * 9 * OCB) * 4u;
        #pragma unroll
        for (int oo = 0; oo < 3; oo++) {
            const int ocl = wrp * 3 + oo;
            const float* wp = w + (size_t)(ocb + ocl) * 900 + icc * 9;
            #pragma unroll
            for (int i = 0; i < 3; i++) {
                const int e = lane + i * 32;
                if (e < 90) cpa4(wb + (unsigned)(e * OCB + ocl) * 4u, wp + e, 4);
            }
        }
    };

    float acc[3][8];
    #pragma unroll
    for (int j = 0; j < 3; j++) {
        const float bv = b[ocb + g * 3 + j];
        #pragma unroll
        for (int p = 0; p < 8; p++) acc[j][p] = bv;
    }

    stage(0, 0);
    cpa_commit();

    for (int c = 0; c < 10; c++) {
        cpa_wait0();
        __syncthreads();
        if (c + 1 < 10) { stage((c + 1) * ICC, (c + 1) & 1); cpa_commit(); }

        const float* bi = s_in + (c & 1) * (ICC * 10 * 36);
        const float* bw = s_w  + (c & 1) * (ICC * 9 * OCB);
        #pragma unroll 2
        for (int ic = 0; ic < ICC; ic++) {
            const float* prow0 = bi + (ic * 10 + ty) * 36 + tx * 8;
            const float* pwic  = bw + ic * 9 * OCB + g * 3;
            #pragma unroll
            for (int ky = 0; ky < 3; ky++) {
                const float* pr = prow0 + ky * 36;
                const float4 v0 = *(const float4*)pr;
                const float4 v1 = *(const float4*)(pr + 4);
                float rr[10];
                rr[0]=v0.x; rr[1]=v0.y; rr[2]=v0.z; rr[3]=v0.w;
                rr[4]=v1.x; rr[5]=v1.y; rr[6]=v1.z; rr[7]=v1.w;
                rr[8]=pr[8]; rr[9]=pr[9];
                #pragma unroll
                for (int kx = 0; kx < 3; kx++) {
                    const float* wp = pwic + (ky * 3 + kx) * OCB;
                    const float w0 = wp[0], w1 = wp[1], w2 = wp[2];
                    #pragma unroll
                    for (int p = 0; p < 8; p++) {
                        const float iv = rr[p + kx];
                        acc[0][p] = fmaf(w0, iv, acc[0][p]);
                        acc[1][p] = fmaf(w1, iv, acc[1][p]);
                        acc[2][p] = fmaf(w2, iv, acc[2][p]);
                    }
                }
            }
        }
    }

    // per-thread partial (3 oc = dx g*3..g*3+2 of patch row z)
    const int d0 = g * 3;
    #pragma unroll
    for (int p = 0; p < 8; p++) {
        const int col = tx * 8 + p;
        const float a0 = acc[0][p], a1 = acc[1][p], a2 = acc[2][p];
        const float* r0 = s_rgb + (0 * 8 + ty) * 52 + col + d0;
        const float* r1 = s_rgb + (1 * 8 + ty) * 52 + col + d0;
        const float* r2 = s_rgb + (2 * 8 + ty) * 52 + col + d0;
        float* sr = s_red + ((g * 8 + ty) * 32 + col) * 4;
        sr[0] = a0 * r0[0] + a1 * r0[1] + a2 * r0[2];
        sr[1] = a0 * r1[0] + a1 * r1[1] + a2 * r1[2];
        sr[2] = a0 * r2[0] + a1 * r2[1] + a2 * r2[2];
        sr[3] = a0 + a1 + a2;
    }
    __syncthreads();

    // deterministic reduction over 7 oc-groups
    for (int idx = tid; idx < 8 * 32 * 4; idx += 224) {
        const int cch = idx & 3;
        const int col = (idx >> 2) & 31;
        const int yy  = idx >> 7;
        float v = 0.f;
        #pragma unroll
        for (int gg = 0; gg < 7; gg++) v += s_red[((gg * 8 + yy) * 32 + col) * 4 + cch];
        g_part[(size_t)(z * 4 + cch) * HWSZ + (y0 + yy) * WW + x0 + col] = v;
    }
}

// ---------------------------------------------------------------------------
__global__ __launch_bounds__(256)
void finalize_k(float* __restrict__ out)
{
    const int i = blockIdx.x * blockDim.x + threadIdx.x;
    if (i >= HWSZ) return;
    float sr = 0.f, sg = 0.f, sb = 0.f, ss = 0.f;
    for (int zz = 0; zz < 21; zz++) {
        const float* p = g_part + (size_t)(zz * 4) * HWSZ + i;
        sr += p[0];
        sg += p[(size_t)HWSZ];
        sb += p[(size_t)2 * HWSZ];
        ss += p[(size_t)3 * HWSZ];
    }
    const float inv = 1.f / (ss + 1e-6f);
    out[i]                    = sr * inv;
    out[(size_t)HWSZ + i]     = sg * inv;
    out[(size_t)2 * HWSZ + i] = sb * inv;
}

// ---------------------------------------------------------------------------
// inputs: input, ref(unused), w0, b0, w_mid, b_mid, w_last, b_last
// ---------------------------------------------------------------------------
extern "C" void kernel_launch(void* const* d_in, const int* in_sizes, int n_in,
                              void* d_out, int out_size)
{
    const float* input  = (const float*)d_in[0];
    const float* w0     = (const float*)d_in[2];
    const float* b0     = (const float*)d_in[3];
    const float* w_mid  = (const float*)d_in[4];
    const float* b_mid  = (const float*)d_in[5];
    const float* w_last = (const float*)d_in[6];
    const float* b_last = (const float*)d_in[7];
    float* out = (float*)d_out;

    cudaFuncSetAttribute(conv3x3_k<10, false>, cudaFuncAttributeMaxDynamicSharedMemorySize, C3_SMEM);
    cudaFuncSetAttribute(conv3x3_k<100, true>, cudaFuncAttributeMaxDynamicSharedMemorySize, C3_SMEM);
    cudaFuncSetAttribute(convlast_k, cudaFuncAttributeMaxDynamicSharedMemorySize, CL_SMEM);

    float *A, *B;
    cudaGetSymbolAddress((void**)&A, g_bufA);
    cudaGetSymbolAddress((void**)&B, g_bufB);

    const dim3 gc(WW / 32, HH / 16, 5);

    conv3x3_k<10, false><<<gc, 320, C3_SMEM>>>(input, w0, b0, A);

    const float* cur = A;
    float* nxt = B;
    for (int l = 0; l < 23; l++) {
        conv3x3_k<100, true><<<gc, 320, C3_SMEM>>>(cur, w_mid + (size_t)l * 90000,
                                                   b_mid + (size_t)l * 100, nxt);
        float* t = (float*)cur; cur = nxt; nxt = t;
    }

    convlast_k<<<dim3(WW / 32, HH / 8, 21), 224, CL_SMEM>>>(cur, input, w_last, b_last);

    finalize_k<<<(HWSZ + 255) / 256, 256>>>(out);
}

// round 6
// speedup vs baseline: 1.4705x; 1.4705x over previous
#include <cuda_runtime.h>
#include <cuda_bf16.h>
#include <cstdint>

#define HH 512
#define WW 1024
#define HWSZ (HH*WW)

// ---------------- device scratch ----------------
__device__ __nv_bfloat16 g_actH[2][(size_t)HWSZ*128];
__device__ __nv_bfloat16 g_actL[2][(size_t)HWSZ*128];
__device__ __nv_bfloat16 g_inH[(size_t)HWSZ*64];
__device__ __nv_bfloat16 g_inL[(size_t)HWSZ*64];
__device__ float g_feat[(size_t)100*HWSZ];
__device__ float g_part[(size_t)21*4*HWSZ];
__device__ __nv_bfloat16 g_wmH[(size_t)23*9*2*104*64];
__device__ __nv_bfloat16 g_wmL[(size_t)23*9*2*104*64];
__device__ __nv_bfloat16 g_w0H[(size_t)9*104*64];
__device__ __nv_bfloat16 g_w0L[(size_t)9*104*64];
__device__ float g_bias[24*104];

// ---------------- helpers ----------------
__device__ __forceinline__ unsigned smem_u32(const void* p){unsigned a;asm("{ .reg .u64 t; cvta.to.shared.u64 t, %1; cvt.u32.u64 %0, t; }":"=r"(a):"l"(p));return a;}
__device__ __forceinline__ void cpa4(unsigned d,const void* s,int sz){asm volatile("cp.async.ca.shared.global [%0], [%1], 4, %2;"::"r"(d),"l"(s),"r"(sz));}
__device__ __forceinline__ void cpa16(unsigned d,const void* s,int sz){asm volatile("cp.async.cg.shared.global [%0], [%1], 16, %2;"::"r"(d),"l"(s),"r"(sz));}
__device__ __forceinline__ void cpa_commit(){asm volatile("cp.async.commit_group;");}
__device__ __forceinline__ void cpa_wait0(){asm volatile("cp.async.wait_group 0;");}
__device__ __forceinline__ void cpa_wait1(){asm volatile("cp.async.wait_group 1;");}
__device__ __forceinline__ unsigned sw128(unsigned o){return o^((o>>3)&0x70);}
__device__ __forceinline__ void ldsm4(uint32_t* r, unsigned a){
    asm volatile("ldmatrix.sync.aligned.m8n8.x4.shared.b16 {%0,%1,%2,%3}, [%4];"
        :"=r"(r[0]),"=r"(r[1]),"=r"(r[2]),"=r"(r[3]):"r"(a));
}
__device__ __forceinline__ void ldsm2(uint32_t* r, unsigned a){
    asm volatile("ldmatrix.sync.aligned.m8n8.x2.shared.b16 {%0,%1}, [%2];"
        :"=r"(r[0]),"=r"(r[1]):"r"(a));
}
__device__ __forceinline__ void mma16816(float* c, const uint32_t* a, const uint32_t* b){
    asm volatile("mma.sync.aligned.m16n8k16.row.col.f32.bf16.bf16.f32 "
        "{%0,%1,%2,%3}, {%4,%5,%6,%7}, {%8,%9}, {%0,%1,%2,%3};"
        :"+f"(c[0]),"+f"(c[1]),"+f"(c[2]),"+f"(c[3])
        :"r"(a[0]),"r"(a[1]),"r"(a[2]),"r"(a[3]),"r"(b[0]),"r"(b[1]));
}

// ---------------- prep kernels ----------------
__global__ void prep_input_k(const float* __restrict__ in){
    const int pix=blockIdx.x*blockDim.x+threadIdx.x; if(pix>=HWSZ) return;
    __nv_bfloat16* ph=g_inH+(size_t)pix*64; __nv_bfloat16* pl=g_inL+(size_t)pix*64;
    #pragma unroll
    for(int c=0;c<64;c++){
        float v=(c<10)?in[(size_t)c*HWSZ+pix]:0.f;
        __nv_bfloat16 h=__float2bfloat16(v); ph[c]=h; pl[c]=__float2bfloat16(v-__bfloat162float(h));
    }
}
__global__ void prep_w0_k(const float* __restrict__ w){
    const int idx=blockIdx.x*blockDim.x+threadIdx.x; if(idx>=9*104*64) return;
    const int j=idx&63, n=(idx>>6)%104, off=(idx>>6)/104;
    float v=(n<100&&j<10)?w[((size_t)n*10+j)*9+off]:0.f;
    __nv_bfloat16 h=__float2bfloat16(v); g_w0H[idx]=h; g_w0L[idx]=__float2bfloat16(v-__bfloat162float(h));
}
__global__ void prep_wmid_k(const float* __restrict__ w){
    const int idx=blockIdx.x*blockDim.x+threadIdx.x; if(idx>=23*9*2*104*64) return;
    const int j=idx&63, n=(idx>>6)%104;
    const int rest=(idx>>6)/104, cb=rest%2, rest2=rest/2, off=rest2%9, l=rest2/9;
    const int ic=cb*64+j;
    float v=(n<100&&ic<100)?w[(((size_t)l*100+n)*100+ic)*9+off]:0.f;
    __nv_bfloat16 h=__float2bfloat16(v); g_wmH[idx]=h; g_wmL[idx]=__float2bfloat16(v-__bfloat162float(h));
}
__global__ void prep_bias_k(const float* __restrict__ b0,const float* __restrict__ bm){
    const int idx=blockIdx.x*blockDim.x+threadIdx.x; if(idx>=24*104) return;
    const int n=idx%104,l=idx/104; g_bias[idx]=(n<100)?(l==0?b0[n]:bm[(l-1)*100+n]):0.f;
}
// zero NHWC pad channels 104..127 of both ping-pong buffers (hi & lo)
__global__ void zpad_k(){
    const int pix=blockIdx.x*blockDim.x+threadIdx.x; if(pix>=HWSZ) return;
    const uint4 z=make_uint4(0,0,0,0);
    #pragma unroll
    for(int b=0;b<2;b++){
        uint4* ph=(uint4*)(g_actH[b]+(size_t)pix*128+104);
        uint4* pl=(uint4*)(g_actL[b]+(size_t)pix*128+104);
        ph[0]=z; ph[1]=z; ph[2]=z; pl[0]=z; pl[1]=z; pl[2]=z;
    }
}

// ---------------------------------------------------------------------------
// Warp-MMA implicit-GEMM conv layer.
// CTA: 256 thr (8 warps = 4 m-rows x 2 n-cols). M=128 px (16x8), N=104 oc.
// Stage = (offset, 64-ch block): A[128][64] hi+lo, B[104][64] hi+lo, SW128 rows,
// cp.async double-buffered. bf16x3 split: hi*hi + hi*lo + lo*hi.
// Stage layout: A_hi 0 | A_lo 16384 | B_hi 32768 | B_lo 46080 ; stride 59392.
// ---------------------------------------------------------------------------
#define SMEM_MM (1024 + 2*59392)

template<int CBIN,int KCN,bool LEAKY,bool LASTF32>
__global__ __launch_bounds__(256)
void convMMA(const __nv_bfloat16* __restrict__ aH,const __nv_bfloat16* __restrict__ aL,
             const __nv_bfloat16* __restrict__ wH,const __nv_bfloat16* __restrict__ wL,
             const float* __restrict__ bias,
             __nv_bfloat16* __restrict__ oH,__nv_bfloat16* __restrict__ oL,float* __restrict__ oF)
{
    constexpr int NST=9*CBIN;
    extern __shared__ char dyn[];
    __shared__ float s_bias[104];
    const int tid=threadIdx.x, lane=tid&31, wid=tid>>5;
    const int wm=wid>>1, wn=wid&1;
    const int x0=blockIdx.x*16, y0=blockIdx.y*8;
    const unsigned sbase=(smem_u32(dyn)+1023u)&~1023u;
    if(tid<104) s_bias[tid]=bias[tid];

    auto loadStage=[&](int s,int buf){
        const int off=s/CBIN, cb=s-off*CBIN;
        const int dy=off/3-1, dx=off%3-1;
        const unsigned base=sbase+(unsigned)buf*59392u;
        #pragma unroll
        for(int k=0;k<15;k++){
            const int idx=tid+k*256;
            if(idx<2048){
                const int hl=idx>>10, r=idx&1023, m=r>>3, i=r&7;
                const int gy=y0+(m>>4)+dy, gx=x0+(m&15)+dx;
                const bool ok=(unsigned)gy<HH&&(unsigned)gx<WW;
                const __nv_bfloat16* src=(hl?aL:aH)+((size_t)(ok?(gy*WW+gx):0))*(CBIN*64)+cb*64+i*8;
                cpa16(base+hl*16384u+sw128((unsigned)(m*128+i*16)),src,ok?16:0);
            } else if(idx<3712){
                const int r=idx-2048; const int hl=r>=832?1:0; const int rr=r-hl*832;
                const int n=rr>>3, i=rr&7;
                const __nv_bfloat16* src=(hl?wL:wH)+((size_t)(off*CBIN+cb)*104+n)*64+i*8;
                cpa16(base+32768u+hl*13312u+sw128((unsigned)(n*128+i*16)),src,16);
            }
        }
    };

    float C[7][2][4];
    #pragma unroll
    for(int t=0;t<7;t++)
        #pragma unroll
        for(int mt=0;mt<2;mt++)
            #pragma unroll
            for(int q=0;q<4;q++) C[t][mt][q]=0.f;

    loadStage(0,0); cpa_commit();
    __syncthreads();

    for(int s=0;s<NST;s++){
        if(s+1<NST){ loadStage(s+1,(s+1)&1); cpa_commit(); cpa_wait1(); }
        else cpa_wait0();
        __syncthreads();

        const unsigned bA=sbase+(unsigned)(s&1)*59392u;
        const unsigned bB=bA+32768u;
        #pragma unroll
        for(int kc=0;kc<KCN;kc++){
            uint32_t ah[2][4], al[2][4], bh[7][2], bl[7][2];
            #pragma unroll
            for(int mt=0;mt<2;mt++){
                const unsigned rb=(unsigned)((wm*32+mt*16+(lane&15))*128 + kc*32 + ((lane&16)?16:0));
                ldsm4(ah[mt], bA+sw128(rb));
                ldsm4(al[mt], bA+16384u+sw128(rb));
            }
            #pragma unroll
            for(int p=0;p<3;p++){
                const unsigned rb=(unsigned)((wn*48+p*16+(lane&7)+((lane&16)?8:0))*128 + kc*32 + ((lane&8)?16:0));
                uint32_t t4[4];
                ldsm4(t4, bB+sw128(rb));
                bh[2*p][0]=t4[0]; bh[2*p][1]=t4[1]; bh[2*p+1][0]=t4[2]; bh[2*p+1][1]=t4[3];
                ldsm4(t4, bB+13312u+sw128(rb));
                bl[2*p][0]=t4[0]; bl[2*p][1]=t4[1]; bl[2*p+1][0]=t4[2]; bl[2*p+1][1]=t4[3];
            }
            {
                const unsigned rb6=(unsigned)((wn*48+48+(lane&7))*128 + kc*32 + ((lane&8)?16:0));
                ldsm2(bh[6], bB+sw128(rb6));
                ldsm2(bl[6], bB+13312u+sw128(rb6));
            }
            #pragma unroll
            for(int t=0;t<7;t++)
                #pragma unroll
                for(int mt=0;mt<2;mt++){
                    mma16816(C[t][mt], ah[mt], bh[t]);
                    mma16816(C[t][mt], ah[mt], bl[t]);
                    mma16816(C[t][mt], al[mt], bh[t]);
                }
        }
        __syncthreads();
    }

    // ---- epilogue ----
    #pragma unroll
    for(int t=0;t<7;t++){
        if(wn==1 && t==0) continue;
        const int n0=wn*48+t*8+2*(lane&3);
        #pragma unroll
        for(int mt=0;mt<2;mt++){
            const int mr=wm*32+mt*16+(lane>>2);
            #pragma unroll
            for(int h=0;h<2;h++){
                const int m=mr+h*8;
                const int pix=(y0+(m>>4))*WW+x0+(m&15);
                float v0=C[t][mt][2*h+0]+s_bias[n0];
                float v1=C[t][mt][2*h+1]+s_bias[n0+1];
                if(LEAKY){ v0=(v0>0.f)?v0:0.01f*v0; v1=(v1>0.f)?v1:0.01f*v1; }
                if(LASTF32){
                    if(n0<100)   oF[(size_t)n0*HWSZ+pix]=v0;
                    if(n0+1<100) oF[(size_t)(n0+1)*HWSZ+pix]=v1;
                } else {
                    __nv_bfloat16 h0=__float2bfloat16(v0), h1=__float2bfloat16(v1);
                    __nv_bfloat16 l0=__float2bfloat16(v0-__bfloat162float(h0));
                    __nv_bfloat16 l1=__float2bfloat16(v1-__bfloat162float(h1));
                    *(uint32_t*)(oH+(size_t)pix*128+n0)=(unsigned)__bfloat16_as_ushort(h0)|((unsigned)__bfloat16_as_ushort(h1)<<16);
                    *(uint32_t*)(oL+(size_t)pix*128+n0)=(unsigned)__bfloat16_as_ushort(l0)|((unsigned)__bfloat16_as_ushort(l1)<<16);
                }
            }
        }
    }
}

// ---------------- convlast (R2, proven) ----------------
#define CL_SIN (2*10*10*36)
#define CL_SW (2*10*9*21)
#define CL_SRGB (3*8*52)
#define CL_SRED (7*8*32*4)
#define CL_SMEM ((CL_SIN+CL_SW+CL_SRGB+CL_SRED)*4)
__global__ __launch_bounds__(224,2)
void convlast_k(const float* __restrict__ feat,const float* __restrict__ rgb,
                const float* __restrict__ w,const float* __restrict__ b)
{
    constexpr int ICC=10, OCB=21;
    extern __shared__ float sm[];
    float* s_in=sm; float* s_w=sm+CL_SIN; float* s_rgb=sm+CL_SIN+CL_SW; float* s_red=sm+CL_SIN+CL_SW+CL_SRGB;
    const int tid=threadIdx.x, wrp=tid>>5, lane=tid&31, g=wrp;
    const int ty=lane>>2, tx=lane&3;
    const int x0=blockIdx.x*32, y0=blockIdx.y*8, z=blockIdx.z, ocb=z*OCB;
    const unsigned sin_a=smem_u32(s_in), sw_a=smem_u32(s_w), srgb_a=smem_u32(s_rgb);
    for(int idx=tid;idx<3*8*52;idx+=224){
        const int xx=idx%52,t1=idx/52,yy=t1%8,cc=t1/8;
        const int gy=y0+yy+z-10,gx=x0+xx-10;
        const bool ok=(unsigned)gy<HH&&(unsigned)gx<WW;
        cpa4(srgb_a+(unsigned)idx*4u,ok?(rgb+(size_t)cc*HWSZ+gy*WW+gx):rgb,ok?4:0);
    }
    auto stage=[&](int icc,int bufi){
        unsigned ib=sin_a+(unsigned)(bufi*ICC*10*36)*4u;
        for(int rid=wrp;rid<100;rid+=7){
            const int ic=rid/10, yy=rid-ic*10, gy=y0+yy-1;
            const bool rowok=(unsigned)gy<HH;
            const float* rp=feat+(size_t)(icc+ic)*HWSZ+(size_t)gy*WW;
            { const int gx=x0+lane-1; const bool ok=rowok&&(unsigned)gx<WW;
              cpa4(ib+(unsigned)((ic*10+yy)*36+lane)*4u,ok?(rp+gx):feat,ok?4:0);}
            if(lane<2){ const int gx=x0+31+lane; const bool ok=rowok&&(unsigned)gx<WW;
              cpa4(ib+(unsigned)((ic*10+yy)*36+32+lane)*4u,ok?(rp+gx):feat,ok?4:0);}
        }
        unsigned wb=sw_a+(unsigned)(bufi*ICC*9*OCB)*4u;
        #pragma unroll
        for(int oo=0;oo<3;oo++){
            const int ocl=wrp*3+oo;
            const float* wp=w+(size_t)(ocb+ocl)*900+icc*9;
            #pragma unroll
            for(int i=0;i<3;i++){const int e=lane+i*32; if(e<90) cpa4(wb+(unsigned)(e*OCB+ocl)*4u,wp+e,4);}
        }
    };
    float acc[3][8];
    #pragma unroll
    for(int j=0;j<3;j++){const float bv=b[ocb+g*3+j];
        #pragma unroll
        for(int p=0;p<8;p++) acc[j][p]=bv;}
    stage(0,0); cpa_commit();
    for(int c=0;c<10;c++){
        cpa_wait0(); __syncthreads();
        if(c+1<10){stage((c+1)*ICC,(c+1)&1); cpa_commit();}
        const float* bi=s_in+(c&1)*(ICC*10*36);
        const float* bw=s_w+(c&1)*(ICC*9*OCB);
        #pragma unroll 2
        for(int ic=0;ic<ICC;ic++){
            const float* prow0=bi+(ic*10+ty)*36+tx*8;
            const float* pwic=bw+ic*9*OCB+g*3;
            #pragma unroll
            for(int ky=0;ky<3;ky++){
                const float* pr=prow0+ky*36;
                const float4 v0=*(const float4*)pr; const float4 v1=*(const float4*)(pr+4);
                float rr[10];
                rr[0]=v0.x;rr[1]=v0.y;rr[2]=v0.z;rr[3]=v0.w;rr[4]=v1.x;rr[5]=v1.y;rr[6]=v1.z;rr[7]=v1.w;rr[8]=pr[8];rr[9]=pr[9];
                #pragma unroll
                for(int kx=0;kx<3;kx++){
                    const float* wp=pwic+(ky*3+kx)*OCB;
                    const float w0=wp[0],w1=wp[1],w2=wp[2];
                    #pragma unroll
                    for(int p=0;p<8;p++){const float iv=rr[p+kx];
                        acc[0][p]=fmaf(w0,iv,acc[0][p]);acc[1][p]=fmaf(w1,iv,acc[1][p]);acc[2][p]=fmaf(w2,iv,acc[2][p]);}
                }
            }
        }
    }
    const int d0=g*3;
    #pragma unroll
    for(int p=0;p<8;p++){
        const int col=tx*8+p;
        const float a0=acc[0][p],a1=acc[1][p],a2=acc[2][p];
        const float* r0=s_rgb+(0*8+ty)*52+col+d0;
        const float* r1=s_rgb+(1*8+ty)*52+col+d0;
        const float* r2=s_rgb+(2*8+ty)*52+col+d0;
        float* sr=s_red+((g*8+ty)*32+col)*4;
        sr[0]=a0*r0[0]+a1*r0[1]+a2*r0[2];
        sr[1]=a0*r1[0]+a1*r1[1]+a2*r1[2];
        sr[2]=a0*r2[0]+a1*r2[1]+a2*r2[2];
        sr[3]=a0+a1+a2;
    }
    __syncthreads();
    for(int idx=tid;idx<8*32*4;idx+=224){
        const int cch=idx&3,col=(idx>>2)&31,yy=idx>>7;
        float v=0.f;
        #pragma unroll
        for(int gg=0;gg<7;gg++) v+=s_red[((gg*8+yy)*32+col)*4+cch];
        g_part[(size_t)(z*4+cch)*HWSZ+(y0+yy)*WW+x0+col]=v;
    }
}

__global__ __launch_bounds__(256)
void finalize_k(float* __restrict__ out){
    const int i=blockIdx.x*blockDim.x+threadIdx.x; if(i>=HWSZ) return;
    float sr=0.f,sg=0.f,sb=0.f,ss=0.f;
    for(int zz=0;zz<21;zz++){
        const float* p=g_part+(size_t)(zz*4)*HWSZ+i;
        sr+=p[0]; sg+=p[(size_t)HWSZ]; sb+=p[(size_t)2*HWSZ]; ss+=p[(size_t)3*HWSZ];
    }
    const float inv=1.f/(ss+1e-6f);
    out[i]=sr*inv; out[(size_t)HWSZ+i]=sg*inv; out[(size_t)2*HWSZ+i]=sb*inv;
}

// ---------------------------------------------------------------------------
extern "C" void kernel_launch(void* const* d_in,const int* in_sizes,int n_in,void* d_out,int out_size)
{
    const float* input=(const float*)d_in[0];
    const float* w0=(const float*)d_in[2];
    const float* b0=(const float*)d_in[3];
    const float* w_mid=(const float*)d_in[4];
    const float* b_mid=(const float*)d_in[5];
    const float* w_last=(const float*)d_in[6];
    const float* b_last=(const float*)d_in[7];
    float* out=(float*)d_out;

    cudaFuncSetAttribute(convMMA<1,1,false,false>,cudaFuncAttributeMaxDynamicSharedMemorySize,SMEM_MM);
    cudaFuncSetAttribute(convMMA<2,4,true,false>,cudaFuncAttributeMaxDynamicSharedMemorySize,SMEM_MM);
    cudaFuncSetAttribute(convMMA<2,4,true,true>,cudaFuncAttributeMaxDynamicSharedMemorySize,SMEM_MM);
    cudaFuncSetAttribute(convlast_k,cudaFuncAttributeMaxDynamicSharedMemorySize,CL_SMEM);

    __nv_bfloat16 *aH,*aL,*iH,*iL,*wmH,*wmL,*w0H,*w0L; float *bias,*feat;
    cudaGetSymbolAddress((void**)&aH,g_actH); cudaGetSymbolAddress((void**)&aL,g_actL);
    cudaGetSymbolAddress((void**)&iH,g_inH);  cudaGetSymbolAddress((void**)&iL,g_inL);
    cudaGetSymbolAddress((void**)&wmH,g_wmH); cudaGetSymbolAddress((void**)&wmL,g_wmL);
    cudaGetSymbolAddress((void**)&w0H,g_w0H); cudaGetSymbolAddress((void**)&w0L,g_w0L);
    cudaGetSymbolAddress((void**)&bias,g_bias); cudaGetSymbolAddress((void**)&feat,g_feat);
    const size_t ACT=(size_t)HWSZ*128;
    const size_t WL=(size_t)9*2*104*64;

    prep_input_k<<<HWSZ/256,256>>>(input);
    prep_w0_k<<<(9*104*64+255)/256,256>>>(w0);
    prep_wmid_k<<<(23*9*2*104*64+255)/256,256>>>(w_mid);
    prep_bias_k<<<(24*104+255)/256,256>>>(b0,b_mid);
    zpad_k<<<HWSZ/256,256>>>();

    const dim3 gmm(WW/16,HH/8);
    convMMA<1,1,false,false><<<gmm,256,SMEM_MM>>>(iH,iL,w0H,w0L,bias,aH,aL,nullptr);
    for(int l=0;l<23;l++){
        const int rd=l&1, wr=1-rd;
        if(l<22)
            convMMA<2,4,true,false><<<gmm,256,SMEM_MM>>>(aH+rd*ACT,aL+rd*ACT,wmH+(size_t)l*WL,wmL+(size_t)l*WL,
                bias+(l+1)*104,aH+wr*ACT,aL+wr*ACT,nullptr);
        else
            convMMA<2,4,true,true><<<gmm,256,SMEM_MM>>>(aH+rd*ACT,aL+rd*ACT,wmH+(size_t)l*WL,wmL+(size_t)l*WL,
                bias+(l+1)*104,nullptr,nullptr,feat);
    }

    convlast_k<<<dim3(WW/32,HH/8,21),224,CL_SMEM>>>(feat,input,w_last,b_last);
    finalize_k<<<(HWSZ+255)/256,256>>>(out);
}

// round 7
// speedup vs baseline: 1.5499x; 1.0539x over previous
#include <cuda_runtime.h>
#include <cuda_bf16.h>
#include <cstdint>

#define HH 512
#define WW 1024
#define HWSZ (HH*WW)

// ---------------- device scratch ----------------
__device__ __nv_bfloat16 g_actH[2][(size_t)HWSZ*128];
__device__ __nv_bfloat16 g_actL[2][(size_t)HWSZ*128];
__device__ __nv_bfloat16 g_inH[(size_t)HWSZ*64];
__device__ __nv_bfloat16 g_inL[(size_t)HWSZ*64];
__device__ float g_feat[(size_t)100*HWSZ];
__device__ float g_part[(size_t)21*4*HWSZ];
__device__ __nv_bfloat16 g_wmH[(size_t)23*9*2*104*64];
__device__ __nv_bfloat16 g_wmL[(size_t)23*9*2*104*64];
__device__ __nv_bfloat16 g_w0H[(size_t)9*104*64];
__device__ __nv_bfloat16 g_w0L[(size_t)9*104*64];
__device__ float g_bias[24*104];

// ---------------- helpers ----------------
__device__ __forceinline__ unsigned smem_u32(const void* p){unsigned a;asm("{ .reg .u64 t; cvta.to.shared.u64 t, %1; cvt.u32.u64 %0, t; }":"=r"(a):"l"(p));return a;}
__device__ __forceinline__ void cpa4(unsigned d,const void* s,int sz){asm volatile("cp.async.ca.shared.global [%0], [%1], 4, %2;"::"r"(d),"l"(s),"r"(sz));}
__device__ __forceinline__ void cpa16(unsigned d,const void* s,int sz){asm volatile("cp.async.cg.shared.global [%0], [%1], 16, %2;"::"r"(d),"l"(s),"r"(sz));}
__device__ __forceinline__ void cpa_commit(){asm volatile("cp.async.commit_group;");}
__device__ __forceinline__ void cpa_wait0(){asm volatile("cp.async.wait_group 0;");}
__device__ __forceinline__ void cpa_wait1(){asm volatile("cp.async.wait_group 1;");}
__device__ __forceinline__ unsigned sw128(unsigned o){return o^((o>>3)&0x70);}
__device__ __forceinline__ void ldsm4(uint32_t* r, unsigned a){
    asm volatile("ldmatrix.sync.aligned.m8n8.x4.shared.b16 {%0,%1,%2,%3}, [%4];"
        :"=r"(r[0]),"=r"(r[1]),"=r"(r[2]),"=r"(r[3]):"r"(a));
}
__device__ __forceinline__ void ldsm2(uint32_t* r, unsigned a){
    asm volatile("ldmatrix.sync.aligned.m8n8.x2.shared.b16 {%0,%1}, [%2];"
        :"=r"(r[0]),"=r"(r[1]):"r"(a));
}
__device__ __forceinline__ void mma16816(float* c, const uint32_t* a, const uint32_t* b){
    asm volatile("mma.sync.aligned.m16n8k16.row.col.f32.bf16.bf16.f32 "
        "{%0,%1,%2,%3}, {%4,%5,%6,%7}, {%8,%9}, {%0,%1,%2,%3};"
        :"+f"(c[0]),"+f"(c[1]),"+f"(c[2]),"+f"(c[3])
        :"r"(a[0]),"r"(a[1]),"r"(a[2]),"r"(a[3]),"r"(b[0]),"r"(b[1]));
}

// ---------------- prep kernels ----------------
__global__ void prep_input_k(const float* __restrict__ in){
    const int pix=blockIdx.x*blockDim.x+threadIdx.x; if(pix>=HWSZ) return;
    __nv_bfloat16* ph=g_inH+(size_t)pix*64; __nv_bfloat16* pl=g_inL+(size_t)pix*64;
    #pragma unroll
    for(int c=0;c<64;c++){
        float v=(c<10)?in[(size_t)c*HWSZ+pix]:0.f;
        __nv_bfloat16 h=__float2bfloat16(v); ph[c]=h; pl[c]=__float2bfloat16(v-__bfloat162float(h));
    }
}
__global__ void prep_w0_k(const float* __restrict__ w){
    const int idx=blockIdx.x*blockDim.x+threadIdx.x; if(idx>=9*104*64) return;
    const int j=idx&63, n=(idx>>6)%104, off=(idx>>6)/104;
    float v=(n<100&&j<10)?w[((size_t)n*10+j)*9+off]:0.f;
    __nv_bfloat16 h=__float2bfloat16(v); g_w0H[idx]=h; g_w0L[idx]=__float2bfloat16(v-__bfloat162float(h));
}
__global__ void prep_wmid_k(const float* __restrict__ w){
    const int idx=blockIdx.x*blockDim.x+threadIdx.x; if(idx>=23*9*2*104*64) return;
    const int j=idx&63, n=(idx>>6)%104;
    const int rest=(idx>>6)/104, cb=rest%2, rest2=rest/2, off=rest2%9, l=rest2/9;
    const int ic=cb*64+j;
    float v=(n<100&&ic<100)?w[(((size_t)l*100+n)*100+ic)*9+off]:0.f;
    __nv_bfloat16 h=__float2bfloat16(v); g_wmH[idx]=h; g_wmL[idx]=__float2bfloat16(v-__bfloat162float(h));
}
__global__ void prep_bias_k(const float* __restrict__ b0,const float* __restrict__ bm){
    const int idx=blockIdx.x*blockDim.x+threadIdx.x; if(idx>=24*104) return;
    const int n=idx%104,l=idx/104; g_bias[idx]=(n<100)?(l==0?b0[n]:bm[(l-1)*100+n]):0.f;
}
__global__ void zpad_k(){
    const int pix=blockIdx.x*blockDim.x+threadIdx.x; if(pix>=HWSZ) return;
    const uint4 z=make_uint4(0,0,0,0);
    #pragma unroll
    for(int b=0;b<2;b++){
        uint4* ph=(uint4*)(g_actH[b]+(size_t)pix*128+104);
        uint4* pl=(uint4*)(g_actL[b]+(size_t)pix*128+104);
        ph[0]=z; ph[1]=z; ph[2]=z; pl[0]=z; pl[1]=z; pl[2]=z;
    }
}

// ---------------------------------------------------------------------------
// Warp-MMA implicit-GEMM conv, halo-resident A.
// CTA: 256 thr (8 warps = 4 m x 2 n). M=128 px (16 wide x 8 high), N=104 oc.
// A: halo tile 10x18 px rows (128B each), hi+lo, per ch-block -> loaded ONCE.
//    3x3 offsets realized via per-lane ldmatrix addresses (+ (dy*18+dx)*128).
// B: [104][64ch] hi+lo per (offset,ch-block), double-buffered cp.async.
// bf16x3 split: hi*hi + hi*lo + lo*hi.
// smem: A halo CBIN*2*23040 (<=92160) | B 2*26624 = 53248.
// ---------------------------------------------------------------------------
#define AHALO 23040u
#define SMEM_MM (1024 + 4*23040 + 2*26624)

template<int CBIN,int KCN,bool LEAKY,bool LASTF32>
__global__ __launch_bounds__(256)
void convMMA(const __nv_bfloat16* __restrict__ aH,const __nv_bfloat16* __restrict__ aL,
             const __nv_bfloat16* __restrict__ wH,const __nv_bfloat16* __restrict__ wL,
             const float* __restrict__ bias,
             __nv_bfloat16* __restrict__ oH,__nv_bfloat16* __restrict__ oL,float* __restrict__ oF)
{
    constexpr int NST=9*CBIN;
    extern __shared__ char dyn[];
    __shared__ float s_bias[104];
    const int tid=threadIdx.x, lane=tid&31, wid=tid>>5;
    const int wm=wid>>1, wn=wid&1;
    const int x0=blockIdx.x*16, y0=blockIdx.y*8;
    const unsigned sbase=(smem_u32(dyn)+1023u)&~1023u;
    const unsigned sA=sbase;
    const unsigned sB=sbase+(unsigned)(CBIN*2)*AHALO;
    if(tid<104) s_bias[tid]=bias[tid];

    // ---- stage A halo once: CBIN*2 planes of 180 rows x 128B ----
    for(int idx=tid; idx<CBIN*2*1440; idx+=256){
        const int seg=idx&7, rowq=idx>>3;
        const int row=rowq%180, q=rowq/180;          // q = cb*2 + hl
        const int cb=q>>1, hl=q&1;
        const int yr=row/18, col=row-yr*18;
        const int gy=y0+yr-1, gx=x0+col-1;
        const bool ok=(unsigned)gy<HH&&(unsigned)gx<WW;
        const __nv_bfloat16* src=(hl?aL:aH)+((size_t)(ok?(gy*WW+gx):0))*(CBIN*64)+cb*64+seg*8;
        cpa16(sA+(unsigned)q*AHALO+sw128((unsigned)(row*128+seg*16)),src,ok?16:0);
    }
    // ---- B stage loader ----
    auto loadB=[&](int s,int buf){
        const int off=s/CBIN, cb=s-off*CBIN;
        const unsigned base=sB+(unsigned)buf*26624u;
        #pragma unroll
        for(int k=0;k<7;k++){
            const int idx=tid+k*256; if(idx>=1664) break;
            const int hl=idx>=832?1:0, rr=idx-hl*832, n=rr>>3, i=rr&7;
            const __nv_bfloat16* src=(hl?wL:wH)+((size_t)(off*CBIN+cb)*104+n)*64+i*8;
            cpa16(base+hl*13312u+sw128((unsigned)(n*128+i*16)),src,16);
        }
    };

    float C[7][2][4];
    #pragma unroll
    for(int t=0;t<7;t++)
        #pragma unroll
        for(int mt=0;mt<2;mt++)
            #pragma unroll
            for(int q=0;q<4;q++) C[t][mt][q]=0.f;

    // per-lane A base rows (mt = 0,1): py = wm*2+mt, px = lane&15
    int brow[2];
    #pragma unroll
    for(int mt=0;mt<2;mt++) brow[mt]=(wm*2+mt+1)*18+(lane&15)+1;
    const unsigned klane=((lane&16)?16u:0u);

    loadB(0,0); cpa_commit();

    for(int s=0;s<NST;s++){
        if(s+1<NST){ loadB(s+1,(s+1)&1); cpa_commit(); cpa_wait1(); }
        else cpa_wait0();
        __syncthreads();

        const int off=s/CBIN, cb=s-off*CBIN;
        const int dy=off/3-1, dx=off%3-1;
        const int rdel=dy*18+dx;
        const unsigned aBh=sA+(unsigned)(cb*2)*AHALO;
        const unsigned aBl=aBh+AHALO;
        const unsigned bB=sB+(unsigned)(s&1)*26624u;

        #pragma unroll
        for(int kc=0;kc<KCN;kc++){
            uint32_t ah[2][4], al[2][4], bh[7][2], bl[7][2];
            #pragma unroll
            for(int mt=0;mt<2;mt++){
                const unsigned rel=(unsigned)((brow[mt]+rdel)*128) + (unsigned)(kc*32) + klane;
                ldsm4(ah[mt], aBh+sw128(rel));
                ldsm4(al[mt], aBl+sw128(rel));
            }
            #pragma unroll
            for(int p=0;p<3;p++){
                const unsigned rb=(unsigned)((wn*48+p*16+(lane&7)+((lane&16)?8:0))*128 + kc*32 + ((lane&8)?16:0));
                uint32_t t4[4];
                ldsm4(t4, bB+sw128(rb));
                bh[2*p][0]=t4[0]; bh[2*p][1]=t4[1]; bh[2*p+1][0]=t4[2]; bh[2*p+1][1]=t4[3];
                ldsm4(t4, bB+13312u+sw128(rb));
                bl[2*p][0]=t4[0]; bl[2*p][1]=t4[1]; bl[2*p+1][0]=t4[2]; bl[2*p+1][1]=t4[3];
            }
            {
                const unsigned rb6=(unsigned)((wn*48+48+(lane&7))*128 + kc*32 + ((lane&8)?16:0));
                ldsm2(bh[6], bB+sw128(rb6));
                ldsm2(bl[6], bB+13312u+sw128(rb6));
            }
            #pragma unroll
            for(int t=0;t<7;t++)
                #pragma unroll
                for(int mt=0;mt<2;mt++){
                    mma16816(C[t][mt], ah[mt], bh[t]);
                    mma16816(C[t][mt], ah[mt], bl[t]);
                    mma16816(C[t][mt], al[mt], bh[t]);
                }
        }
        __syncthreads();
    }

    // ---- epilogue ----
    #pragma unroll
    for(int t=0;t<7;t++){
        if(wn==1 && t==0) continue;
        const int n0=wn*48+t*8+2*(lane&3);
        #pragma unroll
        for(int mt=0;mt<2;mt++){
            const int mr=wm*32+mt*16+(lane>>2);
            #pragma unroll
            for(int h=0;h<2;h++){
                const int m=mr+h*8;
                const int pix=(y0+(m>>4))*WW+x0+(m&15);
                float v0=C[t][mt][2*h+0]+s_bias[n0];
                float v1=C[t][mt][2*h+1]+s_bias[n0+1];
                if(LEAKY){ v0=(v0>0.f)?v0:0.01f*v0; v1=(v1>0.f)?v1:0.01f*v1; }
                if(LASTF32){
                    if(n0<100)   oF[(size_t)n0*HWSZ+pix]=v0;
                    if(n0+1<100) oF[(size_t)(n0+1)*HWSZ+pix]=v1;
                } else {
                    __nv_bfloat16 h0=__float2bfloat16(v0), h1=__float2bfloat16(v1);
                    __nv_bfloat16 l0=__float2bfloat16(v0-__bfloat162float(h0));
                    __nv_bfloat16 l1=__float2bfloat16(v1-__bfloat162float(h1));
                    *(uint32_t*)(oH+(size_t)pix*128+n0)=(unsigned)__bfloat16_as_ushort(h0)|((unsigned)__bfloat16_as_ushort(h1)<<16);
                    *(uint32_t*)(oL+(size_t)pix*128+n0)=(unsigned)__bfloat16_as_ushort(l0)|((unsigned)__bfloat16_as_ushort(l1)<<16);
                }
            }
        }
    }
}

// ---------------- convlast (R2, proven) ----------------
#define CL_SIN (2*10*10*36)
#define CL_SW (2*10*9*21)
#define CL_SRGB (3*8*52)
#define CL_SRED (7*8*32*4)
#define CL_SMEM ((CL_SIN+CL_SW+CL_SRGB+CL_SRED)*4)
__global__ __launch_bounds__(224,2)
void convlast_k(const float* __restrict__ feat,const float* __restrict__ rgb,
                const float* __restrict__ w,const float* __restrict__ b)
{
    constexpr int ICC=10, OCB=21;
    extern __shared__ float sm[];
    float* s_in=sm; float* s_w=sm+CL_SIN; float* s_rgb=sm+CL_SIN+CL_SW; float* s_red=sm+CL_SIN+CL_SW+CL_SRGB;
    const int tid=threadIdx.x, wrp=tid>>5, lane=tid&31, g=wrp;
    const int ty=lane>>2, tx=lane&3;
    const int x0=blockIdx.x*32, y0=blockIdx.y*8, z=blockIdx.z, ocb=z*OCB;
    const unsigned sin_a=smem_u32(s_in), sw_a=smem_u32(s_w), srgb_a=smem_u32(s_rgb);
    for(int idx=tid;idx<3*8*52;idx+=224){
        const int xx=idx%52,t1=idx/52,yy=t1%8,cc=t1/8;
        const int gy=y0+yy+z-10,gx=x0+xx-10;
        const bool ok=(unsigned)gy<HH&&(unsigned)gx<WW;
        cpa4(srgb_a+(unsigned)idx*4u,ok?(rgb+(size_t)cc*HWSZ+gy*WW+gx):rgb,ok?4:0);
    }
    auto stage=[&](int icc,int bufi){
        unsigned ib=sin_a+(unsigned)(bufi*ICC*10*36)*4u;
        for(int rid=wrp;rid<100;rid+=7){
            const int ic=rid/10, yy=rid-ic*10, gy=y0+yy-1;
            const bool rowok=(unsigned)gy<HH;
            const float* rp=feat+(size_t)(icc+ic)*HWSZ+(size_t)gy*WW;
            { const int gx=x0+lane-1; const bool ok=rowok&&(unsigned)gx<WW;
              cpa4(ib+(unsigned)((ic*10+yy)*36+lane)*4u,ok?(rp+gx):feat,ok?4:0);}
            if(lane<2){ const int gx=x0+31+lane; const bool ok=rowok&&(unsigned)gx<WW;
              cpa4(ib+(unsigned)((ic*10+yy)*36+32+lane)*4u,ok?(rp+gx):feat,ok?4:0);}
        }
        unsigned wb=sw_a+(unsigned)(bufi*ICC*9*OCB)*4u;
        #pragma unroll
        for(int oo=0;oo<3;oo++){
            const int ocl=wrp*3+oo;
            const float* wp=w+(size_t)(ocb+ocl)*900+icc*9;
            #pragma unroll
            for(int i=0;i<3;i++){const int e=lane+i*32; if(e<90) cpa4(wb+(unsigned)(e*OCB+ocl)*4u,wp+e,4);}
        }
    };
    float acc[3][8];
    #pragma unroll
    for(int j=0;j<3;j++){const float bv=b[ocb+g*3+j];
        #pragma unroll
        for(int p=0;p<8;p++) acc[j][p]=bv;}
    stage(0,0); cpa_commit();
    for(int c=0;c<10;c++){
        cpa_wait0(); __syncthreads();
        if(c+1<10){stage((c+1)*ICC,(c+1)&1); cpa_commit();}
        const float* bi=s_in+(c&1)*(ICC*10*36);
        const float* bw=s_w+(c&1)*(ICC*9*OCB);
        #pragma unroll 2
        for(int ic=0;ic<ICC;ic++){
            const float* prow0=bi+(ic*10+ty)*36+tx*8;
            const float* pwic=bw+ic*9*OCB+g*3;
            #pragma unroll
            for(int ky=0;ky<3;ky++){
                const float* pr=prow0+ky*36;
                const float4 v0=*(const float4*)pr; const float4 v1=*(const float4*)(pr+4);
                float rr[10];
                rr[0]=v0.x;rr[1]=v0.y;rr[2]=v0.z;rr[3]=v0.w;rr[4]=v1.x;rr[5]=v1.y;rr[6]=v1.z;rr[7]=v1.w;rr[8]=pr[8];rr[9]=pr[9];
                #pragma unroll
                for(int kx=0;kx<3;kx++){
                    const float* wp=pwic+(ky*3+kx)*OCB;
                    const float w0=wp[0],w1=wp[1],w2=wp[2];
                    #pragma unroll
                    for(int p=0;p<8;p++){const float iv=rr[p+kx];
                        acc[0][p]=fmaf(w0,iv,acc[0][p]);acc[1][p]=fmaf(w1,iv,acc[1][p]);acc[2][p]=fmaf(w2,iv,acc[2][p]);}
                }
            }
        }
    }
    const int d0=g*3;
    #pragma unroll
    for(int p=0;p<8;p++){
        const int col=tx*8+p;
        const float a0=acc[0][p],a1=acc[1][p],a2=acc[2][p];
        const float* r0=s_rgb+(0*8+ty)*52+col+d0;
        const float* r1=s_rgb+(1*8+ty)*52+col+d0;
        const float* r2=s_rgb+(2*8+ty)*52+col+d0;
        float* sr=s_red+((g*8+ty)*32+col)*4;
        sr[0]=a0*r0[0]+a1*r0[1]+a2*r0[2];
        sr[1]=a0*r1[0]+a1*r1[1]+a2*r1[2];
        sr[2]=a0*r2[0]+a1*r2[1]+a2*r2[2];
        sr[3]=a0+a1+a2;
    }
    __syncthreads();
    for(int idx=tid;idx<8*32*4;idx+=224){
        const int cch=idx&3,col=(idx>>2)&31,yy=idx>>7;
        float v=0.f;
        #pragma unroll
        for(int gg=0;gg<7;gg++) v+=s_red[((gg*8+yy)*32+col)*4+cch];
        g_part[(size_t)(z*4+cch)*HWSZ+(y0+yy)*WW+x0+col]=v;
    }
}

__global__ __launch_bounds__(256)
void finalize_k(float* __restrict__ out){
    const int i=blockIdx.x*blockDim.x+threadIdx.x; if(i>=HWSZ) return;
    float sr=0.f,sg=0.f,sb=0.f,ss=0.f;
    for(int zz=0;zz<21;zz++){
        const float* p=g_part+(size_t)(zz*4)*HWSZ+i;
        sr+=p[0]; sg+=p[(size_t)HWSZ]; sb+=p[(size_t)2*HWSZ]; ss+=p[(size_t)3*HWSZ];
    }
    const float inv=1.f/(ss+1e-6f);
    out[i]=sr*inv; out[(size_t)HWSZ+i]=sg*inv; out[(size_t)2*HWSZ+i]=sb*inv;
}

// ---------------------------------------------------------------------------
extern "C" void kernel_launch(void* const* d_in,const int* in_sizes,int n_in,void* d_out,int out_size)
{
    const float* input=(const float*)d_in[0];
    const float* w0=(const float*)d_in[2];
    const float* b0=(const float*)d_in[3];
    const float* w_mid=(const float*)d_in[4];
    const float* b_mid=(const float*)d_in[5];
    const float* w_last=(const float*)d_in[6];
    const float* b_last=(const float*)d_in[7];
    float* out=(float*)d_out;

    cudaFuncSetAttribute(convMMA<1,1,false,false>,cudaFuncAttributeMaxDynamicSharedMemorySize,SMEM_MM);
    cudaFuncSetAttribute(convMMA<2,4,true,false>,cudaFuncAttributeMaxDynamicSharedMemorySize,SMEM_MM);
    cudaFuncSetAttribute(convMMA<2,4,true,true>,cudaFuncAttributeMaxDynamicSharedMemorySize,SMEM_MM);
    cudaFuncSetAttribute(convlast_k,cudaFuncAttributeMaxDynamicSharedMemorySize,CL_SMEM);

    __nv_bfloat16 *aH,*aL,*iH,*iL,*wmH,*wmL,*w0H,*w0L; float *bias,*feat;
    cudaGetSymbolAddress((void**)&aH,g_actH); cudaGetSymbolAddress((void**)&aL,g_actL);
    cudaGetSymbolAddress((void**)&iH,g_inH);  cudaGetSymbolAddress((void**)&iL,g_inL);
    cudaGetSymbolAddress((void**)&wmH,g_wmH); cudaGetSymbolAddress((void**)&wmL,g_wmL);
    cudaGetSymbolAddress((void**)&w0H,g_w0H); cudaGetSymbolAddress((void**)&w0L,g_w0L);
    cudaGetSymbolAddress((void**)&bias,g_bias); cudaGetSymbolAddress((void**)&feat,g_feat);
    const size_t ACT=(size_t)HWSZ*128;
    const size_t WL=(size_t)9*2*104*64;

    prep_input_k<<<HWSZ/256,256>>>(input);
    prep_w0_k<<<(9*104*64+255)/256,256>>>(w0);
    prep_wmid_k<<<(23*9*2*104*64+255)/256,256>>>(w_mid);
    prep_bias_k<<<(24*104+255)/256,256>>>(b0,b_mid);
    zpad_k<<<HWSZ/256,256>>>();

    const dim3 gmm(WW/16,HH/8);
    convMMA<1,1,false,false><<<gmm,256,SMEM_MM>>>(iH,iL,w0H,w0L,bias,aH,aL,nullptr);
    for(int l=0;l<23;l++){
        const int rd=l&1, wr=1-rd;
        if(l<22)
            convMMA<2,4,true,false><<<gmm,256,SMEM_MM>>>(aH+rd*ACT,aL+rd*ACT,wmH+(size_t)l*WL,wmL+(size_t)l*WL,
                bias+(l+1)*104,aH+wr*ACT,aL+wr*ACT,nullptr);
        else
            convMMA<2,4,true,true><<<gmm,256,SMEM_MM>>>(aH+rd*ACT,aL+rd*ACT,wmH+(size_t)l*WL,wmL+(size_t)l*WL,
                bias+(l+1)*104,nullptr,nullptr,feat);
    }

    convlast_k<<<dim3(WW/32,HH/8,21),224,CL_SMEM>>>(feat,input,w_last,b_last);
    finalize_k<<<(HWSZ+255)/256,256>>>(out);
}

// round 9
// speedup vs baseline: 1.7702x; 1.1421x over previous
#include <cuda_runtime.h>
#include <cuda_bf16.h>
#include <cstdint>

#define HH 512
#define WW 1024
#define HWSZ (HH*WW)

// ---------------- device scratch ----------------
__device__ __nv_bfloat16 g_actH[2][(size_t)HWSZ*128];
__device__ __nv_bfloat16 g_actL[2][(size_t)HWSZ*128];
__device__ __nv_bfloat16 g_inH[(size_t)HWSZ*64];
__device__ __nv_bfloat16 g_inL[(size_t)HWSZ*64];
__device__ float g_feat[(size_t)100*HWSZ];
__device__ float g_part[(size_t)21*4*HWSZ];
__device__ __nv_bfloat16 g_wmH[(size_t)23*9*2*104*64];
__device__ __nv_bfloat16 g_wmL[(size_t)23*9*2*104*64];
__device__ __nv_bfloat16 g_w0H[(size_t)9*104*64];
__device__ __nv_bfloat16 g_w0L[(size_t)9*104*64];
__device__ float g_bias[24*104];

// ---------------- helpers ----------------
__device__ __forceinline__ unsigned smem_u32(const void* p){unsigned a;asm("{ .reg .u64 t; cvta.to.shared.u64 t, %1; cvt.u32.u64 %0, t; }":"=r"(a):"l"(p));return a;}
__device__ __forceinline__ void cpa4(unsigned d,const void* s,int sz){asm volatile("cp.async.ca.shared.global [%0], [%1], 4, %2;"::"r"(d),"l"(s),"r"(sz));}
__device__ __forceinline__ void cpa16(unsigned d,const void* s,int sz){asm volatile("cp.async.cg.shared.global [%0], [%1], 16, %2;"::"r"(d),"l"(s),"r"(sz));}
__device__ __forceinline__ void cpa_commit(){asm volatile("cp.async.commit_group;");}
__device__ __forceinline__ void cpa_wait0(){asm volatile("cp.async.wait_group 0;");}
__device__ __forceinline__ void cpa_wait1(){asm volatile("cp.async.wait_group 1;");}
__device__ __forceinline__ unsigned sw128(unsigned o){return o^((o>>3)&0x70);}
__device__ __forceinline__ void ldsm4(uint32_t* r, unsigned a){
    asm volatile("ldmatrix.sync.aligned.m8n8.x4.shared.b16 {%0,%1,%2,%3}, [%4];"
        :"=r"(r[0]),"=r"(r[1]),"=r"(r[2]),"=r"(r[3]):"r"(a));
}
__device__ __forceinline__ void ldsm2(uint32_t* r, unsigned a){
    asm volatile("ldmatrix.sync.aligned.m8n8.x2.shared.b16 {%0,%1}, [%2];"
        :"=r"(r[0]),"=r"(r[1]):"r"(a));
}
__device__ __forceinline__ void mma16816(float* c, const uint32_t* a, const uint32_t* b){
    asm volatile("mma.sync.aligned.m16n8k16.row.col.f32.bf16.bf16.f32 "
        "{%0,%1,%2,%3}, {%4,%5,%6,%7}, {%8,%9}, {%0,%1,%2,%3};"
        :"+f"(c[0]),"+f"(c[1]),"+f"(c[2]),"+f"(c[3])
        :"r"(a[0]),"r"(a[1]),"r"(a[2]),"r"(a[3]),"r"(b[0]),"r"(b[1]));
}

// ---------------- prep kernels ----------------
__global__ void prep_input_k(const float* __restrict__ in){
    const int pix=blockIdx.x*blockDim.x+threadIdx.x; if(pix>=HWSZ) return;
    __nv_bfloat16* ph=g_inH+(size_t)pix*64; __nv_bfloat16* pl=g_inL+(size_t)pix*64;
    #pragma unroll
    for(int c=0;c<64;c++){
        float v=(c<10)?in[(size_t)c*HWSZ+pix]:0.f;
        __nv_bfloat16 h=__float2bfloat16(v); ph[c]=h; pl[c]=__float2bfloat16(v-__bfloat162float(h));
    }
}
__global__ void prep_w0_k(const float* __restrict__ w){
    const int idx=blockIdx.x*blockDim.x+threadIdx.x; if(idx>=9*104*64) return;
    const int j=idx&63, n=(idx>>6)%104, off=(idx>>6)/104;
    float v=(n<100&&j<10)?w[((size_t)n*10+j)*9+off]:0.f;
    __nv_bfloat16 h=__float2bfloat16(v); g_w0H[idx]=h; g_w0L[idx]=__float2bfloat16(v-__bfloat162float(h));
}
__global__ void prep_wmid_k(const float* __restrict__ w){
    const int idx=blockIdx.x*blockDim.x+threadIdx.x; if(idx>=23*9*2*104*64) return;
    const int j=idx&63, n=(idx>>6)%104;
    const int rest=(idx>>6)/104, cb=rest%2, rest2=rest/2, off=rest2%9, l=rest2/9;
    const int ic=cb*64+j;
    float v=(n<100&&ic<100)?w[(((size_t)l*100+n)*100+ic)*9+off]:0.f;
    __nv_bfloat16 h=__float2bfloat16(v); g_wmH[idx]=h; g_wmL[idx]=__float2bfloat16(v-__bfloat162float(h));
}
__global__ void prep_bias_k(const float* __restrict__ b0,const float* __restrict__ bm){
    const int idx=blockIdx.x*blockDim.x+threadIdx.x; if(idx>=24*104) return;
    const int n=idx%104,l=idx/104; g_bias[idx]=(n<100)?(l==0?b0[n]:bm[(l-1)*100+n]):0.f;
}
__global__ void zpad_k(){
    const int pix=blockIdx.x*blockDim.x+threadIdx.x; if(pix>=HWSZ) return;
    const uint4 z=make_uint4(0,0,0,0);
    #pragma unroll
    for(int b=0;b<2;b++){
        uint4* ph=(uint4*)(g_actH[b]+(size_t)pix*128+104);
        uint4* pl=(uint4*)(g_actL[b]+(size_t)pix*128+104);
        ph[0]=z; ph[1]=z; ph[2]=z; pl[0]=z; pl[1]=z; pl[2]=z;
    }
}

// ---------------------------------------------------------------------------
// Warp-MMA implicit-GEMM conv, halo-resident A, phased channel blocks.
// CTA: 256 thr (8 warps = 4 m x 2 n). M=128 px (16 wide x 8 high), N=104 oc.
// Phase per 64-ch block: stage A halo (10x18 rows x 128B, hi+lo = 46KB) once,
// then 9 offset stages; B double-buffered. 2 CTAs/SM (smem ~98KB).
// cb=1 skips kc=3 (channels 112..127 are all zero).
// ---------------------------------------------------------------------------
#define AHALO 23040u
#define SMEM_MM (1024 + 2*23040 + 2*26624)

template<int CBIN,bool LEAKY,bool LASTF32>
__global__ __launch_bounds__(256,2)
void convMMA(const __nv_bfloat16* __restrict__ aH,const __nv_bfloat16* __restrict__ aL,
             const __nv_bfloat16* __restrict__ wH,const __nv_bfloat16* __restrict__ wL,
             const float* __restrict__ bias,
             __nv_bfloat16* __restrict__ oH,__nv_bfloat16* __restrict__ oL,float* __restrict__ oF)
{
    extern __shared__ char dyn[];
    __shared__ float s_bias[104];
    const int tid=threadIdx.x, lane=tid&31, wid=tid>>5;
    const int wm=wid>>1, wn=wid&1;
    const int x0=blockIdx.x*16, y0=blockIdx.y*8;
    const unsigned sbase=(smem_u32(dyn)+1023u)&~1023u;
    const unsigned sA=sbase;
    const unsigned sB=sbase+2u*AHALO;
    if(tid<104) s_bias[tid]=bias[tid];

    auto stageA=[&](int cb){
        for(int idx=tid; idx<2880; idx+=256){
            const int seg=idx&7, rowq=idx>>3;       // 0..359
            const int row=rowq%180, hl=rowq/180;
            const int yr=row/18, col=row-yr*18;
            const int gy=y0+yr-1, gx=x0+col-1;
            const bool ok=(unsigned)gy<HH&&(unsigned)gx<WW;
            const __nv_bfloat16* src=(hl?aL:aH)+((size_t)(ok?(gy*WW+gx):0))*(CBIN*64)+cb*64+seg*8;
            cpa16(sA+(unsigned)hl*AHALO+sw128((unsigned)(row*128+seg*16)),src,ok?16:0);
        }
    };
    auto loadB=[&](int off,int cb,int buf){
        const unsigned base=sB+(unsigned)buf*26624u;
        #pragma unroll
        for(int k=0;k<7;k++){
            const int idx=tid+k*256; if(idx>=1664) break;
            const int hl=idx>=832?1:0, rr=idx-hl*832, n=rr>>3, i=rr&7;
            const __nv_bfloat16* src=(hl?wL:wH)+((size_t)(off*CBIN+cb)*104+n)*64+i*8;
            cpa16(base+hl*13312u+sw128((unsigned)(n*128+i*16)),src,16);
        }
    };

    float C[7][2][4];
    #pragma unroll
    for(int t=0;t<7;t++)
        #pragma unroll
        for(int mt=0;mt<2;mt++)
            #pragma unroll
            for(int q=0;q<4;q++) C[t][mt][q]=0.f;

    int brow[2];
    #pragma unroll
    for(int mt=0;mt<2;mt++) brow[mt]=(wm*2+mt+1)*18+(lane&15)+1;
    const unsigned klane=((lane&16)?16u:0u);

    for(int cb=0;cb<CBIN;cb++){
        const int kcmax = (CBIN==1)?1:(cb==0?4:3);
        stageA(cb);
        loadB(0,cb,0); cpa_commit();
        for(int s=0;s<9;s++){
            if(s<8){ loadB(s+1,cb,(s+1)&1); cpa_commit(); cpa_wait1(); }
            else cpa_wait0();
            __syncthreads();

            const int dy=s/3-1, dx=s%3-1;
            const int rdel=dy*18+dx;
            const unsigned bB=sB+(unsigned)(s&1)*26624u;

            for(int kc=0;kc<kcmax;kc++){
                uint32_t ah[2][4], al[2][4], bh[7][2], bl[7][2];
                #pragma unroll
                for(int mt=0;mt<2;mt++){
                    const unsigned rel=(unsigned)((brow[mt]+rdel)*128) + (unsigned)(kc*32) + klane;
                    ldsm4(ah[mt], sA+sw128(rel));
                    ldsm4(al[mt], sA+AHALO+sw128(rel));
                }
                #pragma unroll
                for(int p=0;p<3;p++){
                    const unsigned rb=(unsigned)((wn*48+p*16+(lane&7)+((lane&16)?8:0))*128 + kc*32 + ((lane&8)?16:0));
                    uint32_t t4[4];
                    ldsm4(t4, bB+sw128(rb));
                    bh[2*p][0]=t4[0]; bh[2*p][1]=t4[1]; bh[2*p+1][0]=t4[2]; bh[2*p+1][1]=t4[3];
                    ldsm4(t4, bB+13312u+sw128(rb));
                    bl[2*p][0]=t4[0]; bl[2*p][1]=t4[1]; bl[2*p+1][0]=t4[2]; bl[2*p+1][1]=t4[3];
                }
                {
                    const unsigned rb6=(unsigned)((wn*48+48+(lane&7))*128 + kc*32 + ((lane&8)?16:0));
                    ldsm2(bh[6], bB+sw128(rb6));
                    ldsm2(bl[6], bB+13312u+sw128(rb6));
                }
                #pragma unroll
                for(int t=0;t<7;t++)
                    #pragma unroll
                    for(int mt=0;mt<2;mt++){
                        mma16816(C[t][mt], ah[mt], bh[t]);
                        mma16816(C[t][mt], ah[mt], bl[t]);
                        mma16816(C[t][mt], al[mt], bh[t]);
                    }
            }
            __syncthreads();
        }
    }

    // ---- epilogue ----
    #pragma unroll
    for(int t=0;t<7;t++){
        if(wn==1 && t==0) continue;
        const int n0=wn*48+t*8+2*(lane&3);
        #pragma unroll
        for(int mt=0;mt<2;mt++){
            const int mr=wm*32+mt*16+(lane>>2);
            #pragma unroll
            for(int h=0;h<2;h++){
                const int m=mr+h*8;
                const int pix=(y0+(m>>4))*WW+x0+(m&15);
                float v0=C[t][mt][2*h+0]+s_bias[n0];
                float v1=C[t][mt][2*h+1]+s_bias[n0+1];
                if(LEAKY){ v0=(v0>0.f)?v0:0.01f*v0; v1=(v1>0.f)?v1:0.01f*v1; }
                if(LASTF32){
                    if(n0<100)   oF[(size_t)n0*HWSZ+pix]=v0;
                    if(n0+1<100) oF[(size_t)(n0+1)*HWSZ+pix]=v1;
                } else {
                    __nv_bfloat16 h0=__float2bfloat16(v0), h1=__float2bfloat16(v1);
                    __nv_bfloat16 l0=__float2bfloat16(v0-__bfloat162float(h0));
                    __nv_bfloat16 l1=__float2bfloat16(v1-__bfloat162float(h1));
                    *(uint32_t*)(oH+(size_t)pix*128+n0)=(unsigned)__bfloat16_as_ushort(h0)|((unsigned)__bfloat16_as_ushort(h1)<<16);
                    *(uint32_t*)(oL+(size_t)pix*128+n0)=(unsigned)__bfloat16_as_ushort(l0)|((unsigned)__bfloat16_as_ushort(l1)<<16);
                }
            }
        }
    }
}

// ---------------- convlast (R2, proven) ----------------
#define CL_SIN (2*10*10*36)
#define CL_SW (2*10*9*21)
#define CL_SRGB (3*8*52)
#define CL_SRED (7*8*32*4)
#define CL_SMEM ((CL_SIN+CL_SW+CL_SRGB+CL_SRED)*4)
__global__ __launch_bounds__(224,2)
void convlast_k(const float* __restrict__ feat,const float* __restrict__ rgb,
                const float* __restrict__ w,const float* __restrict__ b)
{
    constexpr int ICC=10, OCB=21;
    extern __shared__ float sm[];
    float* s_in=sm; float* s_w=sm+CL_SIN; float* s_rgb=sm+CL_SIN+CL_SW; float* s_red=sm+CL_SIN+CL_SW+CL_SRGB;
    const int tid=threadIdx.x, wrp=tid>>5, lane=tid&31, g=wrp;
    const int ty=lane>>2, tx=lane&3;
    const int x0=blockIdx.x*32, y0=blockIdx.y*8, z=blockIdx.z, ocb=z*OCB;
    const unsigned sin_a=smem_u32(s_in), sw_a=smem_u32(s_w), srgb_a=smem_u32(s_rgb);
    for(int idx=tid;idx<3*8*52;idx+=224){
        const int xx=idx%52,t1=idx/52,yy=t1%8,cc=t1/8;
        const int gy=y0+yy+z-10,gx=x0+xx-10;
        const bool ok=(unsigned)gy<HH&&(unsigned)gx<WW;
        cpa4(srgb_a+(unsigned)idx*4u,ok?(rgb+(size_t)cc*HWSZ+gy*WW+gx):rgb,ok?4:0);
    }
    auto stage=[&](int icc,int bufi){
        unsigned ib=sin_a+(unsigned)(bufi*ICC*10*36)*4u;
        for(int rid=wrp;rid<100;rid+=7){
            const int ic=rid/10, yy=rid-ic*10, gy=y0+yy-1;
            const bool rowok=(unsigned)gy<HH;
            const float* rp=feat+(size_t)(icc+ic)*HWSZ+(size_t)gy*WW;
            { const int gx=x0+lane-1; const bool ok=rowok&&(unsigned)gx<WW;
              cpa4(ib+(unsigned)((ic*10+yy)*36+lane)*4u,ok?(rp+gx):feat,ok?4:0);}
            if(lane<2){ const int gx=x0+31+lane; const bool ok=rowok&&(unsigned)gx<WW;
              cpa4(ib+(unsigned)((ic*10+yy)*36+32+lane)*4u,ok?(rp+gx):feat,ok?4:0);}
        }
        unsigned wb=sw_a+(unsigned)(bufi*ICC*9*OCB)*4u;
        #pragma unroll
        for(int oo=0;oo<3;oo++){
            const int ocl=wrp*3+oo;
            const float* wp=w+(size_t)(ocb+ocl)*900+icc*9;
            #pragma unroll
            for(int i=0;i<3;i++){const int e=lane+i*32; if(e<90) cpa4(wb+(unsigned)(e*OCB+ocl)*4u,wp+e,4);}
        }
    };
    float acc[3][8];
    #pragma unroll
    for(int j=0;j<3;j++){const float bv=b[ocb+g*3+j];
        #pragma unroll
        for(int p=0;p<8;p++) acc[j][p]=bv;}
    stage(0,0); cpa_commit();
    for(int c=0;c<10;c++){
        cpa_wait0(); __syncthreads();
        if(c+1<10){stage((c+1)*ICC,(c+1)&1); cpa_commit();}
        const float* bi=s_in+(c&1)*(ICC*10*36);
        const float* bw=s_w+(c&1)*(ICC*9*OCB);
        #pragma unroll 2
        for(int ic=0;ic<ICC;ic++){
            const float* prow0=bi+(ic*10+ty)*36+tx*8;
            const float* pwic=bw+ic*9*OCB+g*3;
            #pragma unroll
            for(int ky=0;ky<3;ky++){
                const float* pr=prow0+ky*36;
                const float4 v0=*(const float4*)pr; const float4 v1=*(const float4*)(pr+4);
                float rr[10];
                rr[0]=v0.x;rr[1]=v0.y;rr[2]=v0.z;rr[3]=v0.w;rr[4]=v1.x;rr[5]=v1.y;rr[6]=v1.z;rr[7]=v1.w;rr[8]=pr[8];rr[9]=pr[9];
                #pragma unroll
                for(int kx=0;kx<3;kx++){
                    const float* wp=pwic+(ky*3+kx)*OCB;
                    const float w0=wp[0],w1=wp[1],w2=wp[2];
                    #pragma unroll
                    for(int p=0;p<8;p++){const float iv=rr[p+kx];
                        acc[0][p]=fmaf(w0,iv,acc[0][p]);acc[1][p]=fmaf(w1,iv,acc[1][p]);acc[2][p]=fmaf(w2,iv,acc[2][p]);}
                }
            }
        }
    }
    const int d0=g*3;
    #pragma unroll
    for(int p=0;p<8;p++){
        const int col=tx*8+p;
        const float a0=acc[0][p],a1=acc[1][p],a2=acc[2][p];
        const float* r0=s_rgb+(0*8+ty)*52+col+d0;
        const float* r1=s_rgb+(1*8+ty)*52+col+d0;
        const float* r2=s_rgb+(2*8+ty)*52+col+d0;
        float* sr=s_red+((g*8+ty)*32+col)*4;
        sr[0]=a0*r0[0]+a1*r0[1]+a2*r0[2];
        sr[1]=a0*r1[0]+a1*r1[1]+a2*r1[2];
        sr[2]=a0*r2[0]+a1*r2[1]+a2*r2[2];
        sr[3]=a0+a1+a2;
    }
    __syncthreads();
    for(int idx=tid;idx<8*32*4;idx+=224){
        const int cch=idx&3,col=(idx>>2)&31,yy=idx>>7;
        float v=0.f;
        #pragma unroll
        for(int gg=0;gg<7;gg++) v+=s_red[((gg*8+yy)*32+col)*4+cch];
        g_part[(size_t)(z*4+cch)*HWSZ+(y0+yy)*WW+x0+col]=v;
    }
}

__global__ __launch_bounds__(256)
void finalize_k(float* __restrict__ out){
    const int i=blockIdx.x*blockDim.x+threadIdx.x; if(i>=HWSZ) return;
    float sr=0.f,sg=0.f,sb=0.f,ss=0.f;
    for(int zz=0;zz<21;zz++){
        const float* p=g_part+(size_t)(zz*4)*HWSZ+i;
        sr+=p[0]; sg+=p[(size_t)HWSZ]; sb+=p[(size_t)2*HWSZ]; ss+=p[(size_t)3*HWSZ];
    }
    const float inv=1.f/(ss+1e-6f);
    out[i]=sr*inv; out[(size_t)HWSZ+i]=sg*inv; out[(size_t)2*HWSZ+i]=sb*inv;
}

// ---------------------------------------------------------------------------
extern "C" void kernel_launch(void* const* d_in,const int* in_sizes,int n_in,void* d_out,int out_size)
{
    const float* input=(const float*)d_in[0];
    const float* w0=(const float*)d_in[2];
    const float* b0=(const float*)d_in[3];
    const float* w_mid=(const float*)d_in[4];
    const float* b_mid=(const float*)d_in[5];
    const float* w_last=(const float*)d_in[6];
    const float* b_last=(const float*)d_in[7];
    float* out=(float*)d_out;

    cudaFuncSetAttribute(convMMA<1,false,false>,cudaFuncAttributeMaxDynamicSharedMemorySize,SMEM_MM);
    cudaFuncSetAttribute(convMMA<2,true,false>,cudaFuncAttributeMaxDynamicSharedMemorySize,SMEM_MM);
    cudaFuncSetAttribute(convMMA<2,true,true>,cudaFuncAttributeMaxDynamicSharedMemorySize,SMEM_MM);
    cudaFuncSetAttribute(convlast_k,cudaFuncAttributeMaxDynamicSharedMemorySize,CL_SMEM);

    __nv_bfloat16 *aH,*aL,*iH,*iL,*wmH,*wmL,*w0H,*w0L; float *bias,*feat;
    cudaGetSymbolAddress((void**)&aH,g_actH); cudaGetSymbolAddress((void**)&aL,g_actL);
    cudaGetSymbolAddress((void**)&iH,g_inH);  cudaGetSymbolAddress((void**)&iL,g_inL);
    cudaGetSymbolAddress((void**)&wmH,g_wmH); cudaGetSymbolAddress((void**)&wmL,g_wmL);
    cudaGetSymbolAddress((void**)&w0H,g_w0H); cudaGetSymbolAddress((void**)&w0L,g_w0L);
    cudaGetSymbolAddress((void**)&bias,g_bias); cudaGetSymbolAddress((void**)&feat,g_feat);
    const size_t ACT=(size_t)HWSZ*128;
    const size_t WL=(size_t)9*2*104*64;

    prep_input_k<<<HWSZ/256,256>>>(input);
    prep_w0_k<<<(9*104*64+255)/256,256>>>(w0);
    prep_wmid_k<<<(23*9*2*104*64+255)/256,256>>>(w_mid);
    prep_bias_k<<<(24*104+255)/256,256>>>(b0,b_mid);
    zpad_k<<<HWSZ/256,256>>>();

    const dim3 gmm(WW/16,HH/8);
    convMMA<1,false,false><<<gmm,256,SMEM_MM>>>(iH,iL,w0H,w0L,bias,aH,aL,nullptr);
    for(int l=0;l<23;l++){
        const int rd=l&1, wr=1-rd;
        if(l<22)
            convMMA<2,true,false><<<gmm,256,SMEM_MM>>>(aH+rd*ACT,aL+rd*ACT,wmH+(size_t)l*WL,wmL+(size_t)l*WL,
                bias+(l+1)*104,aH+wr*ACT,aL+wr*ACT,nullptr);
        else
            convMMA<2,true,true><<<gmm,256,SMEM_MM>>>(aH+rd*ACT,aL+rd*ACT,wmH+(size_t)l*WL,wmL+(size_t)l*WL,
                bias+(l+1)*104,nullptr,nullptr,feat);
    }

    convlast_k<<<dim3(WW/32,HH/8,21),224,CL_SMEM>>>(feat,input,w_last,b_last);
    finalize_k<<<(HWSZ+255)/256,256>>>(out);
}

// round 10
// speedup vs baseline: 2.5193x; 1.4232x over previous
#include <cuda_runtime.h>
#include <cuda_bf16.h>
#include <cstdint>

#define HH 512
#define WW 1024
#define HWSZ (HH*WW)

// ---------------- device scratch ----------------
__device__ __nv_bfloat16 g_actH[2][(size_t)HWSZ*128];
__device__ __nv_bfloat16 g_actL[2][(size_t)HWSZ*128];
__device__ __nv_bfloat16 g_inH[(size_t)HWSZ*64];
__device__ __nv_bfloat16 g_inL[(size_t)HWSZ*64];
__device__ float g_W[(size_t)448*HWSZ];
__device__ __nv_bfloat16 g_wmH[(size_t)23*9*2*104*64];
__device__ __nv_bfloat16 g_wmL[(size_t)23*9*2*104*64];
__device__ __nv_bfloat16 g_w0H[(size_t)9*104*64];
__device__ __nv_bfloat16 g_w0L[(size_t)9*104*64];
__device__ __nv_bfloat16 g_wlH[(size_t)9*2*448*64];
__device__ __nv_bfloat16 g_wlL[(size_t)9*2*448*64];
__device__ float g_bias[24*104];
__device__ float g_biasL[448];

// ---------------- helpers ----------------
__device__ __forceinline__ unsigned smem_u32(const void* p){unsigned a;asm("{ .reg .u64 t; cvta.to.shared.u64 t, %1; cvt.u32.u64 %0, t; }":"=r"(a):"l"(p));return a;}
__device__ __forceinline__ void cpa16(unsigned d,const void* s,int sz){asm volatile("cp.async.cg.shared.global [%0], [%1], 16, %2;"::"r"(d),"l"(s),"r"(sz));}
__device__ __forceinline__ void cpa_commit(){asm volatile("cp.async.commit_group;");}
__device__ __forceinline__ void cpa_wait0(){asm volatile("cp.async.wait_group 0;");}
__device__ __forceinline__ void cpa_wait1(){asm volatile("cp.async.wait_group 1;");}
__device__ __forceinline__ unsigned sw128(unsigned o){return o^((o>>3)&0x70);}
__device__ __forceinline__ void ldsm4(uint32_t* r, unsigned a){
    asm volatile("ldmatrix.sync.aligned.m8n8.x4.shared.b16 {%0,%1,%2,%3}, [%4];"
        :"=r"(r[0]),"=r"(r[1]),"=r"(r[2]),"=r"(r[3]):"r"(a));
}
__device__ __forceinline__ void ldsm2(uint32_t* r, unsigned a){
    asm volatile("ldmatrix.sync.aligned.m8n8.x2.shared.b16 {%0,%1}, [%2];"
        :"=r"(r[0]),"=r"(r[1]):"r"(a));
}
__device__ __forceinline__ void mma16816(float* c, const uint32_t* a, const uint32_t* b){
    asm volatile("mma.sync.aligned.m16n8k16.row.col.f32.bf16.bf16.f32 "
        "{%0,%1,%2,%3}, {%4,%5,%6,%7}, {%8,%9}, {%0,%1,%2,%3};"
        :"+f"(c[0]),"+f"(c[1]),"+f"(c[2]),"+f"(c[3])
        :"r"(a[0]),"r"(a[1]),"r"(a[2]),"r"(a[3]),"r"(b[0]),"r"(b[1]));
}
__device__ __forceinline__ uint32_t pack_bf16(float v0,float v1,__nv_bfloat16& h0,__nv_bfloat16& h1){
    h0=__float2bfloat16(v0); h1=__float2bfloat16(v1);
    return (unsigned)__bfloat16_as_ushort(h0)|((unsigned)__bfloat16_as_ushort(h1)<<16);
}

// ---------------- prep kernels (merged: 2 launches) ----------------
#define NW0 (9*104*64)
#define NWM (23*18*104*64)
#define NWL (9*2*448*64)
#define NBM (24*104)
#define NBL 448
__global__ void prepW_k(const float* __restrict__ w0,const float* __restrict__ wm,
                        const float* __restrict__ wl,const float* __restrict__ b0,
                        const float* __restrict__ bm,const float* __restrict__ bl){
    int idx=blockIdx.x*blockDim.x+threadIdx.x;
    if(idx<NW0){
        const int j=idx&63, n=(idx>>6)%104, off=(idx>>6)/104;
        float v=(n<100&&j<10)?w0[((size_t)n*10+j)*9+off]:0.f;
        __nv_bfloat16 h=__float2bfloat16(v); g_w0H[idx]=h; g_w0L[idx]=__float2bfloat16(v-__bfloat162float(h));
        return;
    }
    idx-=NW0;
    if(idx<NWM){
        const int j=idx&63, n=(idx>>6)%104;
        const int rest=(idx>>6)/104, cb=rest%2, rest2=rest/2, off=rest2%9, l=rest2/9;
        const int ic=cb*64+j;
        float v=(n<100&&ic<100)?wm[(((size_t)l*100+n)*100+ic)*9+off]:0.f;
        __nv_bfloat16 h=__float2bfloat16(v); g_wmH[idx]=h; g_wmL[idx]=__float2bfloat16(v-__bfloat162float(h));
        return;
    }
    idx-=NWM;
    if(idx<NWL){
        const int j=idx&63, n=(idx>>6)%448;
        const int rest=(idx>>6)/448, cb=rest%2, off=rest/2;
        const int ic=cb*64+j;
        float v=(n<441&&ic<100)?wl[((size_t)n*100+ic)*9+off]:0.f;
        __nv_bfloat16 h=__float2bfloat16(v); g_wlH[idx]=h; g_wlL[idx]=__float2bfloat16(v-__bfloat162float(h));
        return;
    }
    idx-=NWL;
    if(idx<NBM){
        const int n=idx%104,l=idx/104; g_bias[idx]=(n<100)?(l==0?b0[n]:bm[(l-1)*100+n]):0.f;
        return;
    }
    idx-=NBM;
    if(idx<NBL) g_biasL[idx]=(idx<441)?bl[idx]:0.f;
}
__global__ void prepI_k(const float* __restrict__ in){
    const int pix=blockIdx.x*blockDim.x+threadIdx.x; if(pix>=HWSZ) return;
    __nv_bfloat16* ph=g_inH+(size_t)pix*64; __nv_bfloat16* pl=g_inL+(size_t)pix*64;
    #pragma unroll
    for(int c=0;c<64;c++){
        float v=(c<10)?in[(size_t)c*HWSZ+pix]:0.f;
        __nv_bfloat16 h=__float2bfloat16(v); ph[c]=h; pl[c]=__float2bfloat16(v-__bfloat162float(h));
    }
    const uint4 z=make_uint4(0,0,0,0);
    #pragma unroll
    for(int b=0;b<2;b++){
        uint4* qh=(uint4*)(g_actH[b]+(size_t)pix*128+104);
        uint4* ql=(uint4*)(g_actL[b]+(size_t)pix*128+104);
        qh[0]=z; qh[1]=z; qh[2]=z; ql[0]=z; ql[1]=z; ql[2]=z;
    }
}

// ---------------------------------------------------------------------------
// Warp-MMA implicit-GEMM conv, halo-resident A, phased channel blocks,
// smem-staged coalesced epilogue. 2 CTAs/SM.
// ---------------------------------------------------------------------------
#define AHALO 23040u
#define SMEM_MM (1024 + 2*23040 + 2*26624)

template<int CBIN,bool LEAKY>
__global__ __launch_bounds__(256,2)
void convMMA(const __nv_bfloat16* __restrict__ aH,const __nv_bfloat16* __restrict__ aL,
             const __nv_bfloat16* __restrict__ wH,const __nv_bfloat16* __restrict__ wL,
             const float* __restrict__ bias,
             __nv_bfloat16* __restrict__ oH,__nv_bfloat16* __restrict__ oL)
{
    extern __shared__ char dyn[];
    __shared__ float s_bias[104];
    const int tid=threadIdx.x, lane=tid&31, wid=tid>>5;
    const int wm=wid>>1, wn=wid&1;
    const int x0=blockIdx.x*16, y0=blockIdx.y*8;
    char* dynp=(char*)(((uintptr_t)dyn+1023)&~(uintptr_t)1023);
    const unsigned sbase=smem_u32(dynp);
    const unsigned sA=sbase;
    const unsigned sB=sbase+2u*AHALO;
    if(tid<104) s_bias[tid]=bias[tid];

    auto stageA=[&](int cb){
        for(int idx=tid; idx<2880; idx+=256){
            const int seg=idx&7, rowq=idx>>3;
            const int row=rowq%180, hl=rowq/180;
            const int yr=row/18, col=row-yr*18;
            const int gy=y0+yr-1, gx=x0+col-1;
            const bool ok=(unsigned)gy<HH&&(unsigned)gx<WW;
            const __nv_bfloat16* src=(hl?aL:aH)+((size_t)(ok?(gy*WW+gx):0))*(CBIN*64)+cb*64+seg*8;
            cpa16(sA+(unsigned)hl*AHALO+sw128((unsigned)(row*128+seg*16)),src,ok?16:0);
        }
    };
    auto loadB=[&](int off,int cb,int buf){
        const unsigned base=sB+(unsigned)buf*26624u;
        #pragma unroll
        for(int k=0;k<7;k++){
            const int idx=tid+k*256; if(idx>=1664) break;
            const int hl=idx>=832?1:0, rr=idx-hl*832, n=rr>>3, i=rr&7;
            const __nv_bfloat16* src=(hl?wL:wH)+((size_t)(off*CBIN+cb)*104+n)*64+i*8;
            cpa16(base+hl*13312u+sw128((unsigned)(n*128+i*16)),src,16);
        }
    };

    float C[7][2][4];
    #pragma unroll
    for(int t=0;t<7;t++)
        #pragma unroll
        for(int mt=0;mt<2;mt++)
            #pragma unroll
            for(int q=0;q<4;q++) C[t][mt][q]=0.f;

    int brow[2];
    #pragma unroll
    for(int mt=0;mt<2;mt++) brow[mt]=(wm*2+mt+1)*18+(lane&15)+1;
    const unsigned klane=((lane&16)?16u:0u);

    for(int cb=0;cb<CBIN;cb++){
        const int kcmax = (CBIN==1)?1:(cb==0?4:3);
        stageA(cb);
        loadB(0,cb,0); cpa_commit();
        for(int s=0;s<9;s++){
            if(s<8){ loadB(s+1,cb,(s+1)&1); cpa_commit(); cpa_wait1(); }
            else cpa_wait0();
            __syncthreads();

            const int dy=s/3-1, dx=s%3-1;
            const int rdel=dy*18+dx;
            const unsigned bB=sB+(unsigned)(s&1)*26624u;

            for(int kc=0;kc<kcmax;kc++){
                uint32_t ah[2][4], al[2][4], bh[7][2], bl[7][2];
                #pragma unroll
                for(int mt=0;mt<2;mt++){
                    const unsigned rel=(unsigned)((brow[mt]+rdel)*128) + (unsigned)(kc*32) + klane;
                    ldsm4(ah[mt], sA+sw128(rel));
                    ldsm4(al[mt], sA+AHALO+sw128(rel));
                }
                #pragma unroll
                for(int p=0;p<3;p++){
                    const unsigned rb=(unsigned)((wn*48+p*16+(lane&7)+((lane&16)?8:0))*128 + kc*32 + ((lane&8)?16:0));
                    uint32_t t4[4];
                    ldsm4(t4, bB+sw128(rb));
                    bh[2*p][0]=t4[0]; bh[2*p][1]=t4[1]; bh[2*p+1][0]=t4[2]; bh[2*p+1][1]=t4[3];
                    ldsm4(t4, bB+13312u+sw128(rb));
                    bl[2*p][0]=t4[0]; bl[2*p][1]=t4[1]; bl[2*p+1][0]=t4[2]; bl[2*p+1][1]=t4[3];
                }
                {
                    const unsigned rb6=(unsigned)((wn*48+48+(lane&7))*128 + kc*32 + ((lane&8)?16:0));
                    ldsm2(bh[6], bB+sw128(rb6));
                    ldsm2(bl[6], bB+13312u+sw128(rb6));
                }
                #pragma unroll
                for(int t=0;t<7;t++)
                    #pragma unroll
                    for(int mt=0;mt<2;mt++){
                        mma16816(C[t][mt], ah[mt], bh[t]);
                        mma16816(C[t][mt], ah[mt], bl[t]);
                        mma16816(C[t][mt], al[mt], bh[t]);
                    }
            }
            __syncthreads();
        }
    }

    // ---- epilogue: stage in smem, coalesced uint4 stores ----
    char* s_hi=dynp;            // [128 px][104 bf16] = 208B rows
    char* s_lo=dynp+26624;
    #pragma unroll
    for(int t=0;t<7;t++){
        if(wn==1 && t==0) continue;
        const int n0=wn*48+t*8+2*(lane&3);
        #pragma unroll
        for(int mt=0;mt<2;mt++){
            const int mr=wm*32+mt*16+(lane>>2);
            #pragma unroll
            for(int h=0;h<2;h++){
                const int m=mr+h*8;
                float v0=C[t][mt][2*h+0]+s_bias[n0];
                float v1=C[t][mt][2*h+1]+s_bias[n0+1];
                if(LEAKY){ v0=(v0>0.f)?v0:0.01f*v0; v1=(v1>0.f)?v1:0.01f*v1; }
                __nv_bfloat16 h0,h1;
                const uint32_t hp=pack_bf16(v0,v1,h0,h1);
                const uint32_t lp=pack_bf16(v0-__bfloat162float(h0),v1-__bfloat162float(h1),h0,h1);
                *(uint32_t*)(s_hi + m*208 + n0*2)=hp;
                *(uint32_t*)(s_lo + m*208 + n0*2)=lp;
            }
        }
    }
    __syncthreads();
    for(int idx=tid; idx<3328; idx+=256){
        const int buf=idx>=1664; const int r=idx-buf*1664;
        const int px=r/13, q=r-px*13;
        const uint4 val=*(uint4*)((buf?s_lo:s_hi) + px*208 + q*16);
        const int pix=(y0+(px>>4))*WW+x0+(px&15);
        *(uint4*)((buf?oL:oH)+(size_t)pix*128+q*8)=val;
    }
}

// ---------------------------------------------------------------------------
// conv_last as MMA: N=112 per z-pass (z=0..3 covers 448 oc), writes planar
// fp32 W[448][HW] via smem-transposed coalesced stores.
// ---------------------------------------------------------------------------
#define SMEM_CL (1024 + 2*23040 + 2*28672)
__global__ __launch_bounds__(256,2)
void convlastMMA(const __nv_bfloat16* __restrict__ aH,const __nv_bfloat16* __restrict__ aL)
{
    extern __shared__ char dyn[];
    __shared__ float s_bias[112];
    const int tid=threadIdx.x, lane=tid&31, wid=tid>>5;
    const int wm=wid>>1, wn=wid&1;
    const int x0=blockIdx.x*16, y0=blockIdx.y*8, z=blockIdx.z;
    char* dynp=(char*)(((uintptr_t)dyn+1023)&~(uintptr_t)1023);
    const unsigned sbase=smem_u32(dynp);
    const unsigned sA=sbase;
    const unsigned sB=sbase+2u*AHALO;
    if(tid<112) s_bias[tid]=g_biasL[z*112+tid];

    auto stageA=[&](int cb){
        for(int idx=tid; idx<2880; idx+=256){
            const int seg=idx&7, rowq=idx>>3;
            const int row=rowq%180, hl=rowq/180;
            const int yr=row/18, col=row-yr*18;
            const int gy=y0+yr-1, gx=x0+col-1;
            const bool ok=(unsigned)gy<HH&&(unsigned)gx<WW;
            const __nv_bfloat16* src=(hl?aL:aH)+((size_t)(ok?(gy*WW+gx):0))*128+cb*64+seg*8;
            cpa16(sA+(unsigned)hl*AHALO+sw128((unsigned)(row*128+seg*16)),src,ok?16:0);
        }
    };
    auto loadB=[&](int off,int cb,int buf){
        const unsigned base=sB+(unsigned)buf*28672u;
        #pragma unroll
        for(int k=0;k<7;k++){
            const int idx=tid+k*256;
            const int hl=idx>=896?1:0, rr=idx-hl*896, n=rr>>3, i=rr&7;
            const __nv_bfloat16* src=(hl?g_wlL:g_wlH)+((size_t)(off*2+cb)*448+z*112+n)*64+i*8;
            cpa16(base+hl*14336u+sw128((unsigned)(n*128+i*16)),src,16);
        }
    };

    float C[7][2][4];
    #pragma unroll
    for(int t=0;t<7;t++)
        #pragma unroll
        for(int mt=0;mt<2;mt++)
            #pragma unroll
            for(int q=0;q<4;q++) C[t][mt][q]=0.f;

    int brow[2];
    #pragma unroll
    for(int mt=0;mt<2;mt++) brow[mt]=(wm*2+mt+1)*18+(lane&15)+1;
    const unsigned klane=((lane&16)?16u:0u);

    for(int cb=0;cb<2;cb++){
        const int kcmax = (cb==0)?4:3;
        stageA(cb);
        loadB(0,cb,0); cpa_commit();
        for(int s=0;s<9;s++){
            if(s<8){ loadB(s+1,cb,(s+1)&1); cpa_commit(); cpa_wait1(); }
            else cpa_wait0();
            __syncthreads();

            const int dy=s/3-1, dx=s%3-1;
            const int rdel=dy*18+dx;
            const unsigned bB=sB+(unsigned)(s&1)*28672u;

            for(int kc=0;kc<kcmax;kc++){
                uint32_t ah[2][4], al[2][4], bh[7][2], bl[7][2];
                #pragma unroll
                for(int mt=0;mt<2;mt++){
                    const unsigned rel=(unsigned)((brow[mt]+rdel)*128) + (unsigned)(kc*32) + klane;
                    ldsm4(ah[mt], sA+sw128(rel));
                    ldsm4(al[mt], sA+AHALO+sw128(rel));
                }
                #pragma unroll
                for(int p=0;p<3;p++){
                    const unsigned rb=(unsigned)((wn*56+p*16+(lane&7)+((lane&16)?8:0))*128 + kc*32 + ((lane&8)?16:0));
                    uint32_t t4[4];
                    ldsm4(t4, bB+sw128(rb));
                    bh[2*p][0]=t4[0]; bh[2*p][1]=t4[1]; bh[2*p+1][0]=t4[2]; bh[2*p+1][1]=t4[3];
                    ldsm4(t4, bB+14336u+sw128(rb));
                    bl[2*p][0]=t4[0]; bl[2*p][1]=t4[1]; bl[2*p+1][0]=t4[2]; bl[2*p+1][1]=t4[3];
                }
                {
                    const unsigned rb6=(unsigned)((wn*56+48+(lane&7))*128 + kc*32 + ((lane&8)?16:0));
                    ldsm2(bh[6], bB+sw128(rb6));
                    ldsm2(bl[6], bB+14336u+sw128(rb6));
                }
                #pragma unroll
                for(int t=0;t<7;t++)
                    #pragma unroll
                    for(int mt=0;mt<2;mt++){
                        mma16816(C[t][mt], ah[mt], bh[t]);
                        mma16816(C[t][mt], ah[mt], bl[t]);
                        mma16816(C[t][mt], al[mt], bh[t]);
                    }
            }
            __syncthreads();
        }
    }

    // ---- epilogue: s_W[112 oc][128 px] fp32, planar coalesced stores ----
    float* s_W=(float*)dynp;
    #pragma unroll
    for(int t=0;t<7;t++){
        const int n0=wn*56+t*8+2*(lane&3);
        #pragma unroll
        for(int mt=0;mt<2;mt++){
            const int mr=wm*32+mt*16+(lane>>2);
            #pragma unroll
            for(int h=0;h<2;h++){
                const int m=mr+h*8;
                s_W[n0*128+m]    =C[t][mt][2*h+0]+s_bias[n0];
                s_W[(n0+1)*128+m]=C[t][mt][2*h+1]+s_bias[n0+1];
            }
        }
    }
    __syncthreads();
    for(int idx=tid; idx<112*32; idx+=256){
        const int oc=idx>>5, c=idx&31;
        const int px0=c*4;
        const uint4 val=*(uint4*)(s_W+oc*128+px0);
        const int pix=(y0+(px0>>4))*WW+x0+(px0&15);
        *(uint4*)(g_W+(size_t)(z*112+oc)*HWSZ+pix)=val;
    }
}

// ---------------------------------------------------------------------------
// Kernel regression: out[c] = sum_k W[k]*rgb(shift_k) / (sum_k W[k] + eps)
// ---------------------------------------------------------------------------
__global__ __launch_bounds__(256)
void regress_k(const float* __restrict__ rgb, float* __restrict__ out)
{
    __shared__ float s_rgb[3][28][52];
    const int tid=threadIdx.x;
    const int tx=tid&31, ty=tid>>5;
    const int x0=blockIdx.x*32, y0=blockIdx.y*8;
    for(int idx=tid; idx<3*28*52; idx+=256){
        const int cl=idx%52, t1=idx/52;
        const int rr=t1%28, cc=t1/28;
        const int gy=y0+rr-10, gx=x0+cl-10;
        s_rgb[cc][rr][cl]=((unsigned)gy<HH&&(unsigned)gx<WW)?rgb[(size_t)cc*HWSZ+gy*WW+gx]:0.f;
    }
    __syncthreads();
    const int pix=(y0+ty)*WW+x0+tx;
    float sr=0.f,sg=0.f,sb=0.f,ss=0.f;
    const float* wp=g_W+pix;
    int k=0;
    for(int dy=0;dy<21;dy++){
        const float* r0=&s_rgb[0][ty+dy][tx];
        const float* r1=&s_rgb[1][ty+dy][tx];
        const float* r2=&s_rgb[2][ty+dy][tx];
        #pragma unroll
        for(int dx=0;dx<21;dx++){
            const float wk=wp[(size_t)k*HWSZ];
            sr=fmaf(wk,r0[dx],sr); sg=fmaf(wk,r1[dx],sg); sb=fmaf(wk,r2[dx],sb); ss+=wk;
            k++;
        }
    }
    const float inv=1.f/(ss+1e-6f);
    out[pix]=sr*inv; out[(size_t)HWSZ+pix]=sg*inv; out[(size_t)2*HWSZ+pix]=sb*inv;
}

// ---------------------------------------------------------------------------
extern "C" void kernel_launch(void* const* d_in,const int* in_sizes,int n_in,void* d_out,int out_size)
{
    const float* input=(const float*)d_in[0];
    const float* w0=(const float*)d_in[2];
    const float* b0=(const float*)d_in[3];
    const float* w_mid=(const float*)d_in[4];
    const float* b_mid=(const float*)d_in[5];
    const float* w_last=(const float*)d_in[6];
    const float* b_last=(const float*)d_in[7];
    float* out=(float*)d_out;

    cudaFuncSetAttribute(convMMA<1,false>,cudaFuncAttributeMaxDynamicSharedMemorySize,SMEM_MM);
    cudaFuncSetAttribute(convMMA<2,true>,cudaFuncAttributeMaxDynamicSharedMemorySize,SMEM_MM);
    cudaFuncSetAttribute(convlastMMA,cudaFuncAttributeMaxDynamicSharedMemorySize,SMEM_CL);

    __nv_bfloat16 *aH,*aL,*iH,*iL,*wmH,*wmL,*w0H,*w0L; float *bias;
    cudaGetSymbolAddress((void**)&aH,g_actH); cudaGetSymbolAddress((void**)&aL,g_actL);
    cudaGetSymbolAddress((void**)&iH,g_inH);  cudaGetSymbolAddress((void**)&iL,g_inL);
    cudaGetSymbolAddress((void**)&wmH,g_wmH); cudaGetSymbolAddress((void**)&wmL,g_wmL);
    cudaGetSymbolAddress((void**)&w0H,g_w0H); cudaGetSymbolAddress((void**)&w0L,g_w0L);
    cudaGetSymbolAddress((void**)&bias,g_bias);
    const size_t ACT=(size_t)HWSZ*128;
    const size_t WL=(size_t)9*2*104*64;

    const int NPREP=NW0+NWM+NWL+NBM+NBL;
    prepW_k<<<(NPREP+255)/256,256>>>(w0,w_mid,w_last,b0,b_mid,b_last);
    prepI_k<<<HWSZ/256,256>>>(input);

    const dim3 gmm(WW/16,HH/8);
    convMMA<1,false><<<gmm,256,SMEM_MM>>>(iH,iL,w0H,w0L,bias,aH,aL);
    for(int l=0;l<23;l++){
        const int rd=l&1, wr=1-rd;
        convMMA<2,true><<<gmm,256,SMEM_MM>>>(aH+rd*ACT,aL+rd*ACT,wmH+(size_t)l*WL,wmL+(size_t)l*WL,
            bias+(l+1)*104,aH+wr*ACT,aL+wr*ACT);
    }
    // features are in buffer 1 after 23 mid layers
    convlastMMA<<<dim3(WW/16,HH/8,4),256,SMEM_CL>>>(aH+ACT,aL+ACT);

    regress_k<<<dim3(WW/32,HH/8),256>>>(input,out);
}

// round 11
// speedup vs baseline: 2.5863x; 1.0266x over previous
#include <cuda_runtime.h>
#include <cuda_bf16.h>
#include <cstdint>

#define HH 512
#define WW 1024
#define HWSZ (HH*WW)

// ---------------- device scratch ----------------
__device__ __nv_bfloat16 g_actH[2][(size_t)HWSZ*128];
__device__ __nv_bfloat16 g_actL[2][(size_t)HWSZ*128];
__device__ __nv_bfloat16 g_inH[(size_t)HWSZ*64];
__device__ __nv_bfloat16 g_inL[(size_t)HWSZ*64];
__device__ float g_W[(size_t)448*HWSZ];
__device__ __nv_bfloat16 g_wmH[(size_t)23*9*2*104*64];
__device__ __nv_bfloat16 g_wmL[(size_t)23*9*2*104*64];
__device__ __nv_bfloat16 g_w0H[(size_t)9*104*64];
__device__ __nv_bfloat16 g_w0L[(size_t)9*104*64];
__device__ __nv_bfloat16 g_wlH[(size_t)9*2*448*64];
__device__ __nv_bfloat16 g_wlL[(size_t)9*2*448*64];
__device__ float g_bias[24*104];
__device__ float g_biasL[448];

// ---------------- helpers ----------------
__device__ __forceinline__ unsigned smem_u32(const void* p){unsigned a;asm("{ .reg .u64 t; cvta.to.shared.u64 t, %1; cvt.u32.u64 %0, t; }":"=r"(a):"l"(p));return a;}
__device__ __forceinline__ void cpa16(unsigned d,const void* s,int sz){asm volatile("cp.async.cg.shared.global [%0], [%1], 16, %2;"::"r"(d),"l"(s),"r"(sz));}
__device__ __forceinline__ void cpa_commit(){asm volatile("cp.async.commit_group;");}
__device__ __forceinline__ void cpa_wait0(){asm volatile("cp.async.wait_group 0;");}
__device__ __forceinline__ unsigned sw128(unsigned o){return o^((o>>3)&0x70);}
__device__ __forceinline__ void ldsm4(uint32_t* r, unsigned a){
    asm volatile("ldmatrix.sync.aligned.m8n8.x4.shared.b16 {%0,%1,%2,%3}, [%4];"
        :"=r"(r[0]),"=r"(r[1]),"=r"(r[2]),"=r"(r[3]):"r"(a));
}
__device__ __forceinline__ void ldsm2(uint32_t* r, unsigned a){
    asm volatile("ldmatrix.sync.aligned.m8n8.x2.shared.b16 {%0,%1}, [%2];"
        :"=r"(r[0]),"=r"(r[1]):"r"(a));
}
__device__ __forceinline__ void mma16816(float* c, const uint32_t* a, const uint32_t* b){
    asm volatile("mma.sync.aligned.m16n8k16.row.col.f32.bf16.bf16.f32 "
        "{%0,%1,%2,%3}, {%4,%5,%6,%7}, {%8,%9}, {%0,%1,%2,%3};"
        :"+f"(c[0]),"+f"(c[1]),"+f"(c[2]),"+f"(c[3])
        :"r"(a[0]),"r"(a[1]),"r"(a[2]),"r"(a[3]),"r"(b[0]),"r"(b[1]));
}
__device__ __forceinline__ uint32_t pack_bf16(float v0,float v1,__nv_bfloat16& h0,__nv_bfloat16& h1){
    h0=__float2bfloat16(v0); h1=__float2bfloat16(v1);
    return (unsigned)__bfloat16_as_ushort(h0)|((unsigned)__bfloat16_as_ushort(h1)<<16);
}

#define AHALO 23040u

// Fully-unrolled compute for one (offset, ch-block) stage.
// Pass-major mma order: 14 independent mmas between dependent pairs.
template<int KCMAX>
__device__ __forceinline__ void computeStage(
    unsigned sA, unsigned bB, unsigned bLoff, int rdel,
    int brow0, int brow1, unsigned klane, int nbase, int lane,
    float C[7][2][4])
{
    const int br[2]={brow0,brow1};
    #pragma unroll
    for(int kc=0;kc<KCMAX;kc++){
        uint32_t ah[2][4], al[2][4], bh[7][2], bl[7][2];
        #pragma unroll
        for(int mt=0;mt<2;mt++){
            const unsigned rel=(unsigned)((br[mt]+rdel)*128)+(unsigned)(kc*32)+klane;
            ldsm4(ah[mt], sA+sw128(rel));
            ldsm4(al[mt], sA+AHALO+sw128(rel));
        }
        #pragma unroll
        for(int p=0;p<3;p++){
            const unsigned rb=(unsigned)((nbase+p*16+(lane&7)+((lane&16)?8:0))*128 + kc*32 + ((lane&8)?16:0));
            uint32_t t4[4];
            ldsm4(t4, bB+sw128(rb));
            bh[2*p][0]=t4[0]; bh[2*p][1]=t4[1]; bh[2*p+1][0]=t4[2]; bh[2*p+1][1]=t4[3];
            ldsm4(t4, bB+bLoff+sw128(rb));
            bl[2*p][0]=t4[0]; bl[2*p][1]=t4[1]; bl[2*p+1][0]=t4[2]; bl[2*p+1][1]=t4[3];
        }
        {
            const unsigned rb6=(unsigned)((nbase+48+(lane&7))*128 + kc*32 + ((lane&8)?16:0));
            ldsm2(bh[6], bB+sw128(rb6));
            ldsm2(bl[6], bB+bLoff+sw128(rb6));
        }
        #pragma unroll
        for(int t=0;t<7;t++)
            #pragma unroll
            for(int mt=0;mt<2;mt++) mma16816(C[t][mt], ah[mt], bh[t]);
        #pragma unroll
        for(int t=0;t<7;t++)
            #pragma unroll
            for(int mt=0;mt<2;mt++) mma16816(C[t][mt], ah[mt], bl[t]);
        #pragma unroll
        for(int t=0;t<7;t++)
            #pragma unroll
            for(int mt=0;mt<2;mt++) mma16816(C[t][mt], al[mt], bh[t]);
    }
}

// ---------------- prep kernels ----------------
#define NW0 (9*104*64)
#define NWM (23*18*104*64)
#define NWL (9*2*448*64)
#define NBM (24*104)
#define NBL 448
__global__ void prepW_k(const float* __restrict__ w0,const float* __restrict__ wm,
                        const float* __restrict__ wl,const float* __restrict__ b0,
                        const float* __restrict__ bm,const float* __restrict__ bl){
    int idx=blockIdx.x*blockDim.x+threadIdx.x;
    if(idx<NW0){
        const int j=idx&63, n=(idx>>6)%104, off=(idx>>6)/104;
        float v=(n<100&&j<10)?w0[((size_t)n*10+j)*9+off]:0.f;
        __nv_bfloat16 h=__float2bfloat16(v); g_w0H[idx]=h; g_w0L[idx]=__float2bfloat16(v-__bfloat162float(h));
        return;
    }
    idx-=NW0;
    if(idx<NWM){
        const int j=idx&63, n=(idx>>6)%104;
        const int rest=(idx>>6)/104, cb=rest%2, rest2=rest/2, off=rest2%9, l=rest2/9;
        const int ic=cb*64+j;
        float v=(n<100&&ic<100)?wm[(((size_t)l*100+n)*100+ic)*9+off]:0.f;
        __nv_bfloat16 h=__float2bfloat16(v); g_wmH[idx]=h; g_wmL[idx]=__float2bfloat16(v-__bfloat162float(h));
        return;
    }
    idx-=NWM;
    if(idx<NWL){
        const int j=idx&63, n=(idx>>6)%448;
        const int rest=(idx>>6)/448, cb=rest%2, off=rest/2;
        const int ic=cb*64+j;
        float v=(n<441&&ic<100)?wl[((size_t)n*100+ic)*9+off]:0.f;
        __nv_bfloat16 h=__float2bfloat16(v); g_wlH[idx]=h; g_wlL[idx]=__float2bfloat16(v-__bfloat162float(h));
        return;
    }
    idx-=NWL;
    if(idx<NBM){
        const int n=idx%104,l=idx/104; g_bias[idx]=(n<100)?(l==0?b0[n]:bm[(l-1)*100+n]):0.f;
        return;
    }
    idx-=NBM;
    if(idx<NBL) g_biasL[idx]=(idx<441)?bl[idx]:0.f;
}
__global__ void prepI_k(const float* __restrict__ in){
    const int pix=blockIdx.x*blockDim.x+threadIdx.x; if(pix>=HWSZ) return;
    __nv_bfloat16* ph=g_inH+(size_t)pix*64; __nv_bfloat16* pl=g_inL+(size_t)pix*64;
    #pragma unroll
    for(int c=0;c<64;c++){
        float v=(c<10)?in[(size_t)c*HWSZ+pix]:0.f;
        __nv_bfloat16 h=__float2bfloat16(v); ph[c]=h; pl[c]=__float2bfloat16(v-__bfloat162float(h));
    }
    const uint4 z=make_uint4(0,0,0,0);
    #pragma unroll
    for(int b=0;b<2;b++){
        uint4* qh=(uint4*)(g_actH[b]+(size_t)pix*128+104);
        uint4* ql=(uint4*)(g_actL[b]+(size_t)pix*128+104);
        qh[0]=z; qh[1]=z; qh[2]=z; ql[0]=z; ql[1]=z; ql[2]=z;
    }
}

// ---------------------------------------------------------------------------
// Warp-MMA implicit-GEMM conv: halo-resident A, phased ch-blocks,
// single sync per stage, unrolled compute. 2 CTAs/SM.
// ---------------------------------------------------------------------------
#define SMEM_MM (1024 + 2*23040 + 2*26624)

template<int CBIN,bool LEAKY>
__global__ __launch_bounds__(256,2)
void convMMA(const __nv_bfloat16* __restrict__ aH,const __nv_bfloat16* __restrict__ aL,
             const __nv_bfloat16* __restrict__ wH,const __nv_bfloat16* __restrict__ wL,
             const float* __restrict__ bias,
             __nv_bfloat16* __restrict__ oH,__nv_bfloat16* __restrict__ oL)
{
    extern __shared__ char dyn[];
    __shared__ float s_bias[104];
    const int tid=threadIdx.x, lane=tid&31, wid=tid>>5;
    const int wm=wid>>1, wn=wid&1;
    const int x0=blockIdx.x*16, y0=blockIdx.y*8;
    char* dynp=(char*)(((uintptr_t)dyn+1023)&~(uintptr_t)1023);
    const unsigned sbase=smem_u32(dynp);
    const unsigned sA=sbase;
    const unsigned sB=sbase+2u*AHALO;
    if(tid<104) s_bias[tid]=bias[tid];

    auto stageA=[&](int cb){
        for(int idx=tid; idx<2880; idx+=256){
            const int seg=idx&7, rowq=idx>>3;
            const int row=rowq%180, hl=rowq/180;
            const int yr=row/18, col=row-yr*18;
            const int gy=y0+yr-1, gx=x0+col-1;
            const bool ok=(unsigned)gy<HH&&(unsigned)gx<WW;
            const __nv_bfloat16* src=(hl?aL:aH)+((size_t)(ok?(gy*WW+gx):0))*(CBIN*64)+cb*64+seg*8;
            cpa16(sA+(unsigned)hl*AHALO+sw128((unsigned)(row*128+seg*16)),src,ok?16:0);
        }
    };
    auto loadB=[&](int off,int cb,int buf){
        const unsigned base=sB+(unsigned)buf*26624u;
        #pragma unroll
        for(int k=0;k<7;k++){
            const int idx=tid+k*256; if(idx>=1664) break;
            const int hl=idx>=832?1:0, rr=idx-hl*832, n=rr>>3, i=rr&7;
            const __nv_bfloat16* src=(hl?wL:wH)+((size_t)(off*CBIN+cb)*104+n)*64+i*8;
            cpa16(base+hl*13312u+sw128((unsigned)(n*128+i*16)),src,16);
        }
    };

    float C[7][2][4];
    #pragma unroll
    for(int t=0;t<7;t++)
        #pragma unroll
        for(int mt=0;mt<2;mt++)
            #pragma unroll
            for(int q=0;q<4;q++) C[t][mt][q]=0.f;

    const int brow0=(wm*2+0+1)*18+(lane&15)+1;
    const int brow1=(wm*2+1+1)*18+(lane&15)+1;
    const unsigned klane=((lane&16)?16u:0u);
    const int nbase=wn*48;

    for(int cb=0;cb<CBIN;cb++){
        if(cb>0) __syncthreads();            // protect A halo reuse
        stageA(cb);
        loadB(0,cb,0);
        cpa_commit();
        for(int s=0;s<9;s++){
            cpa_wait0();
            __syncthreads();
            if(s<8){ loadB(s+1,cb,(s+1)&1); cpa_commit(); }
            const int rdel=(s/3-1)*18+(s%3-1);
            const unsigned bB=sB+(unsigned)(s&1)*26624u;
            if(CBIN==1)      computeStage<1>(sA,bB,13312u,rdel,brow0,brow1,klane,nbase,lane,C);
            else if(cb==0)   computeStage<4>(sA,bB,13312u,rdel,brow0,brow1,klane,nbase,lane,C);
            else             computeStage<3>(sA,bB,13312u,rdel,brow0,brow1,klane,nbase,lane,C);
        }
    }
    __syncthreads();

    // ---- epilogue: stage in smem, coalesced uint4 stores ----
    char* s_hi=dynp;
    char* s_lo=dynp+26624;
    #pragma unroll
    for(int t=0;t<7;t++){
        if(wn==1 && t==0) continue;
        const int n0=wn*48+t*8+2*(lane&3);
        #pragma unroll
        for(int mt=0;mt<2;mt++){
            const int mr=wm*32+mt*16+(lane>>2);
            #pragma unroll
            for(int h=0;h<2;h++){
                const int m=mr+h*8;
                float v0=C[t][mt][2*h+0]+s_bias[n0];
                float v1=C[t][mt][2*h+1]+s_bias[n0+1];
                if(LEAKY){ v0=(v0>0.f)?v0:0.01f*v0; v1=(v1>0.f)?v1:0.01f*v1; }
                __nv_bfloat16 h0,h1;
                const uint32_t hp=pack_bf16(v0,v1,h0,h1);
                const uint32_t lp=pack_bf16(v0-__bfloat162float(h0),v1-__bfloat162float(h1),h0,h1);
                *(uint32_t*)(s_hi + m*208 + n0*2)=hp;
                *(uint32_t*)(s_lo + m*208 + n0*2)=lp;
            }
        }
    }
    __syncthreads();
    for(int idx=tid; idx<3328; idx+=256){
        const int buf=idx>=1664; const int r=idx-buf*1664;
        const int px=r/13, q=r-px*13;
        const uint4 val=*(uint4*)((buf?s_lo:s_hi) + px*208 + q*16);
        const int pix=(y0+(px>>4))*WW+x0+(px&15);
        *(uint4*)((buf?oL:oH)+(size_t)pix*128+q*8)=val;
    }
}

// ---------------------------------------------------------------------------
// conv_last as MMA: N=112 per z-pass (z=0..3), planar fp32 W output.
// ---------------------------------------------------------------------------
#define SMEM_CL (1024 + 2*23040 + 2*28672)
__global__ __launch_bounds__(256,2)
void convlastMMA(const __nv_bfloat16* __restrict__ aH,const __nv_bfloat16* __restrict__ aL)
{
    extern __shared__ char dyn[];
    __shared__ float s_bias[112];
    const int tid=threadIdx.x, lane=tid&31, wid=tid>>5;
    const int wm=wid>>1, wn=wid&1;
    const int x0=blockIdx.x*16, y0=blockIdx.y*8, z=blockIdx.z;
    char* dynp=(char*)(((uintptr_t)dyn+1023)&~(uintptr_t)1023);
    const unsigned sbase=smem_u32(dynp);
    const unsigned sA=sbase;
    const unsigned sB=sbase+2u*AHALO;
    if(tid<112) s_bias[tid]=g_biasL[z*112+tid];

    auto stageA=[&](int cb){
        for(int idx=tid; idx<2880; idx+=256){
            const int seg=idx&7, rowq=idx>>3;
            const int row=rowq%180, hl=rowq/180;
            const int yr=row/18, col=row-yr*18;
            const int gy=y0+yr-1, gx=x0+col-1;
            const bool ok=(unsigned)gy<HH&&(unsigned)gx<WW;
            const __nv_bfloat16* src=(hl?aL:aH)+((size_t)(ok?(gy*WW+gx):0))*128+cb*64+seg*8;
            cpa16(sA+(unsigned)hl*AHALO+sw128((unsigned)(row*128+seg*16)),src,ok?16:0);
        }
    };
    auto loadB=[&](int off,int cb,int buf){
        const unsigned base=sB+(unsigned)buf*28672u;
        #pragma unroll
        for(int k=0;k<7;k++){
            const int idx=tid+k*256;
            const int hl=idx>=896?1:0, rr=idx-hl*896, n=rr>>3, i=rr&7;
            const __nv_bfloat16* src=(hl?g_wlL:g_wlH)+((size_t)(off*2+cb)*448+z*112+n)*64+i*8;
            cpa16(base+hl*14336u+sw128((unsigned)(n*128+i*16)),src,16);
        }
    };

    float C[7][2][4];
    #pragma unroll
    for(int t=0;t<7;t++)
        #pragma unroll
        for(int mt=0;mt<2;mt++)
            #pragma unroll
            for(int q=0;q<4;q++) C[t][mt][q]=0.f;

    const int brow0=(wm*2+0+1)*18+(lane&15)+1;
    const int brow1=(wm*2+1+1)*18+(lane&15)+1;
    const unsigned klane=((lane&16)?16u:0u);
    const int nbase=wn*56;

    for(int cb=0;cb<2;cb++){
        if(cb>0) __syncthreads();
        stageA(cb);
        loadB(0,cb,0);
        cpa_commit();
        for(int s=0;s<9;s++){
            cpa_wait0();
            __syncthreads();
            if(s<8){ loadB(s+1,cb,(s+1)&1); cpa_commit(); }
            const int rdel=(s/3-1)*18+(s%3-1);
            const unsigned bB=sB+(unsigned)(s&1)*28672u;
            if(cb==0) computeStage<4>(sA,bB,14336u,rdel,brow0,brow1,klane,nbase,lane,C);
            else      computeStage<3>(sA,bB,14336u,rdel,brow0,brow1,klane,nbase,lane,C);
        }
    }
    __syncthreads();

    // ---- epilogue: s_W[112 oc][128 px] fp32, planar coalesced stores ----
    float* s_W=(float*)dynp;
    #pragma unroll
    for(int t=0;t<7;t++){
        const int n0=wn*56+t*8+2*(lane&3);
        #pragma unroll
        for(int mt=0;mt<2;mt++){
            const int mr=wm*32+mt*16+(lane>>2);
            #pragma unroll
            for(int h=0;h<2;h++){
                const int m=mr+h*8;
                s_W[n0*128+m]    =C[t][mt][2*h+0]+s_bias[n0];
                s_W[(n0+1)*128+m]=C[t][mt][2*h+1]+s_bias[n0+1];
            }
        }
    }
    __syncthreads();
    for(int idx=tid; idx<112*32; idx+=256){
        const int oc=idx>>5, c=idx&31;
        const int px0=c*4;
        const uint4 val=*(uint4*)(s_W+oc*128+px0);
        const int pix=(y0+(px0>>4))*WW+x0+(px0&15);
        *(uint4*)(g_W+(size_t)(z*112+oc)*HWSZ+pix)=val;
    }
}

// ---------------------------------------------------------------------------
// Kernel regression
// ---------------------------------------------------------------------------
__global__ __launch_bounds__(256)
void regress_k(const float* __restrict__ rgb, float* __restrict__ out)
{
    __shared__ float s_rgb[3][28][52];
    const int tid=threadIdx.x;
    const int tx=tid&31, ty=tid>>5;
    const int x0=blockIdx.x*32, y0=blockIdx.y*8;
    for(int idx=tid; idx<3*28*52; idx+=256){
        const int cl=idx%52, t1=idx/52;
        const int rr=t1%28, cc=t1/28;
        const int gy=y0+rr-10, gx=x0+cl-10;
        s_rgb[cc][rr][cl]=((unsigned)gy<HH&&(unsigned)gx<WW)?rgb[(size_t)cc*HWSZ+gy*WW+gx]:0.f;
    }
    __syncthreads();
    const int pix=(y0+ty)*WW+x0+tx;
    float sr=0.f,sg=0.f,sb=0.f,ss=0.f;
    const float* wp=g_W+pix;
    int k=0;
    for(int dy=0;dy<21;dy++){
        const float* r0=&s_rgb[0][ty+dy][tx];
        const float* r1=&s_rgb[1][ty+dy][tx];
        const float* r2=&s_rgb[2][ty+dy][tx];
        #pragma unroll
        for(int dx=0;dx<21;dx++){
            const float wk=wp[(size_t)k*HWSZ];
            sr=fmaf(wk,r0[dx],sr); sg=fmaf(wk,r1[dx],sg); sb=fmaf(wk,r2[dx],sb); ss+=wk;
            k++;
        }
    }
    const float inv=1.f/(ss+1e-6f);
    out[pix]=sr*inv; out[(size_t)HWSZ+pix]=sg*inv; out[(size_t)2*HWSZ+pix]=sb*inv;
}

// ---------------------------------------------------------------------------
extern "C" void kernel_launch(void* const* d_in,const int* in_sizes,int n_in,void* d_out,int out_size)
{
    const float* input=(const float*)d_in[0];
    const float* w0=(const float*)d_in[2];
    const float* b0=(const float*)d_in[3];
    const float* w_mid=(const float*)d_in[4];
    const float* b_mid=(const float*)d_in[5];
    const float* w_last=(const float*)d_in[6];
    const float* b_last=(const float*)d_in[7];
    float* out=(float*)d_out;

    cudaFuncSetAttribute(convMMA<1,false>,cudaFuncAttributeMaxDynamicSharedMemorySize,SMEM_MM);
    cudaFuncSetAttribute(convMMA<2,true>,cudaFuncAttributeMaxDynamicSharedMemorySize,SMEM_MM);
    cudaFuncSetAttribute(convlastMMA,cudaFuncAttributeMaxDynamicSharedMemorySize,SMEM_CL);

    __nv_bfloat16 *aH,*aL,*iH,*iL,*wmH,*wmL,*w0H,*w0L; float *bias;
    cudaGetSymbolAddress((void**)&aH,g_actH); cudaGetSymbolAddress((void**)&aL,g_actL);
    cudaGetSymbolAddress((void**)&iH,g_inH);  cudaGetSymbolAddress((void**)&iL,g_inL);
    cudaGetSymbolAddress((void**)&wmH,g_wmH); cudaGetSymbolAddress((void**)&wmL,g_wmL);
    cudaGetSymbolAddress((void**)&w0H,g_w0H); cudaGetSymbolAddress((void**)&w0L,g_w0L);
    cudaGetSymbolAddress((void**)&bias,g_bias);
    const size_t ACT=(size_t)HWSZ*128;
    const size_t WL=(size_t)9*2*104*64;

    const int NPREP=NW0+NWM+NWL+NBM+NBL;
    prepW_k<<<(NPREP+255)/256,256>>>(w0,w_mid,w_last,b0,b_mid,b_last);
    prepI_k<<<HWSZ/256,256>>>(input);

    const dim3 gmm(WW/16,HH/8);
    convMMA<1,false><<<gmm,256,SMEM_MM>>>(iH,iL,w0H,w0L,bias,aH,aL);
    for(int l=0;l<23;l++){
        const int rd=l&1, wr=1-rd;
        convMMA<2,true><<<gmm,256,SMEM_MM>>>(aH+rd*ACT,aL+rd*ACT,wmH+(size_t)l*WL,wmL+(size_t)l*WL,
            bias+(l+1)*104,aH+wr*ACT,aL+wr*ACT);
    }
    convlastMMA<<<dim3(WW/16,HH/8,4),256,SMEM_CL>>>(aH+ACT,aL+ACT);

    regress_k<<<dim3(WW/32,HH/8),256>>>(input,out);
}

// round 12
// speedup vs baseline: 2.6382x; 1.0201x over previous
#include <cuda_runtime.h>
#include <cuda_bf16.h>
#include <cstdint>

#define HH 512
#define WW 1024
#define HWSZ (HH*WW)

// ---------------- device scratch ----------------
__device__ __nv_bfloat16 g_actH[2][(size_t)HWSZ*128];
__device__ __nv_bfloat16 g_actL[2][(size_t)HWSZ*128];
__device__ __nv_bfloat16 g_inH[(size_t)HWSZ*64];
__device__ __nv_bfloat16 g_inL[(size_t)HWSZ*64];
__device__ float g_W[(size_t)448*HWSZ];
__device__ __nv_bfloat16 g_wmH[(size_t)23*9*2*104*64];
__device__ __nv_bfloat16 g_wmL[(size_t)23*9*2*104*64];
__device__ __nv_bfloat16 g_w0H[(size_t)9*104*64];
__device__ __nv_bfloat16 g_w0L[(size_t)9*104*64];
__device__ __nv_bfloat16 g_wlH[(size_t)9*2*448*64];
__device__ __nv_bfloat16 g_wlL[(size_t)9*2*448*64];
__device__ float g_bias[24*104];
__device__ float g_biasL[448];

// ---------------- helpers ----------------
__device__ __forceinline__ unsigned smem_u32(const void* p){unsigned a;asm("{ .reg .u64 t; cvta.to.shared.u64 t, %1; cvt.u32.u64 %0, t; }":"=r"(a):"l"(p));return a;}
__device__ __forceinline__ void cpa16(unsigned d,const void* s,int sz){asm volatile("cp.async.cg.shared.global [%0], [%1], 16, %2;"::"r"(d),"l"(s),"r"(sz));}
__device__ __forceinline__ void cpa_commit(){asm volatile("cp.async.commit_group;");}
__device__ __forceinline__ void cpa_wait0(){asm volatile("cp.async.wait_group 0;");}
__device__ __forceinline__ unsigned sw128(unsigned o){return o^((o>>3)&0x70);}
__device__ __forceinline__ void ldsm4(uint32_t* r, unsigned a){
    asm volatile("ldmatrix.sync.aligned.m8n8.x4.shared.b16 {%0,%1,%2,%3}, [%4];"
        :"=r"(r[0]),"=r"(r[1]),"=r"(r[2]),"=r"(r[3]):"r"(a));
}
__device__ __forceinline__ void ldsm2(uint32_t* r, unsigned a){
    asm volatile("ldmatrix.sync.aligned.m8n8.x2.shared.b16 {%0,%1}, [%2];"
        :"=r"(r[0]),"=r"(r[1]):"r"(a));
}
__device__ __forceinline__ void mma16816(float* c, const uint32_t* a, const uint32_t* b){
    asm volatile("mma.sync.aligned.m16n8k16.row.col.f32.bf16.bf16.f32 "
        "{%0,%1,%2,%3}, {%4,%5,%6,%7}, {%8,%9}, {%0,%1,%2,%3};"
        :"+f"(c[0]),"+f"(c[1]),"+f"(c[2]),"+f"(c[3])
        :"r"(a[0]),"r"(a[1]),"r"(a[2]),"r"(a[3]),"r"(b[0]),"r"(b[1]));
}
__device__ __forceinline__ uint32_t pack_bf16(float v0,float v1,__nv_bfloat16& h0,__nv_bfloat16& h1){
    h0=__float2bfloat16(v0); h1=__float2bfloat16(v1);
    return (unsigned)__bfloat16_as_ushort(h0)|((unsigned)__bfloat16_as_ushort(h1)<<16);
}

#define AHALO 23040u

// Fully-unrolled compute for one (offset, ch-block) stage.
// NT = number of 8-oc tiles this warp-column owns (7 or 6).
// Pass-major mma order for latency hiding.
template<int KCMAX,int NT>
__device__ __forceinline__ void computeStage(
    unsigned sA, unsigned bB, unsigned bLoff, int rdel,
    int brow0, int brow1, unsigned klane, int nbase, int lane,
    float C[7][2][4])
{
    const int br[2]={brow0,brow1};
    #pragma unroll
    for(int kc=0;kc<KCMAX;kc++){
        uint32_t ah[2][4], al[2][4], bh[7][2], bl[7][2];
        #pragma unroll
        for(int mt=0;mt<2;mt++){
            const unsigned rel=(unsigned)((br[mt]+rdel)*128)+(unsigned)(kc*32)+klane;
            ldsm4(ah[mt], sA+sw128(rel));
            ldsm4(al[mt], sA+AHALO+sw128(rel));
        }
        constexpr int NP=NT/2;
        #pragma unroll
        for(int p=0;p<NP;p++){
            const unsigned rb=(unsigned)((nbase+p*16+(lane&7)+((lane&16)?8:0))*128 + kc*32 + ((lane&8)?16:0));
            uint32_t t4[4];
            ldsm4(t4, bB+sw128(rb));
            bh[2*p][0]=t4[0]; bh[2*p][1]=t4[1]; bh[2*p+1][0]=t4[2]; bh[2*p+1][1]=t4[3];
            ldsm4(t4, bB+bLoff+sw128(rb));
            bl[2*p][0]=t4[0]; bl[2*p][1]=t4[1]; bl[2*p+1][0]=t4[2]; bl[2*p+1][1]=t4[3];
        }
        if(NT&1){
            const unsigned rb6=(unsigned)((nbase+(NP*16)+(lane&7))*128 + kc*32 + ((lane&8)?16:0));
            ldsm2(bh[NT-1], bB+sw128(rb6));
            ldsm2(bl[NT-1], bB+bLoff+sw128(rb6));
        }
        #pragma unroll
        for(int t=0;t<NT;t++)
            #pragma unroll
            for(int mt=0;mt<2;mt++) mma16816(C[t][mt], ah[mt], bh[t]);
        #pragma unroll
        for(int t=0;t<NT;t++)
            #pragma unroll
            for(int mt=0;mt<2;mt++) mma16816(C[t][mt], ah[mt], bl[t]);
        #pragma unroll
        for(int t=0;t<NT;t++)
            #pragma unroll
            for(int mt=0;mt<2;mt++) mma16816(C[t][mt], al[mt], bh[t]);
    }
}

// ---------------- prep kernels ----------------
#define NW0 (9*104*64)
#define NWM (23*18*104*64)
#define NWL (9*2*448*64)
#define NBM (24*104)
#define NBL 448
__global__ void prepW_k(const float* __restrict__ w0,const float* __restrict__ wm,
                        const float* __restrict__ wl,const float* __restrict__ b0,
                        const float* __restrict__ bm,const float* __restrict__ bl){
    int idx=blockIdx.x*blockDim.x+threadIdx.x;
    if(idx<NW0){
        const int j=idx&63, n=(idx>>6)%104, off=(idx>>6)/104;
        float v=(n<100&&j<10)?w0[((size_t)n*10+j)*9+off]:0.f;
        __nv_bfloat16 h=__float2bfloat16(v); g_w0H[idx]=h; g_w0L[idx]=__float2bfloat16(v-__bfloat162float(h));
        return;
    }
    idx-=NW0;
    if(idx<NWM){
        const int j=idx&63, n=(idx>>6)%104;
        const int rest=(idx>>6)/104, cb=rest%2, rest2=rest/2, off=rest2%9, l=rest2/9;
        const int ic=cb*64+j;
        float v=(n<100&&ic<100)?wm[(((size_t)l*100+n)*100+ic)*9+off]:0.f;
        __nv_bfloat16 h=__float2bfloat16(v); g_wmH[idx]=h; g_wmL[idx]=__float2bfloat16(v-__bfloat162float(h));
        return;
    }
    idx-=NWM;
    if(idx<NWL){
        const int j=idx&63, n=(idx>>6)%448;
        const int rest=(idx>>6)/448, cb=rest%2, off=rest/2;
        const int ic=cb*64+j;
        float v=(n<441&&ic<100)?wl[((size_t)n*100+ic)*9+off]:0.f;
        __nv_bfloat16 h=__float2bfloat16(v); g_wlH[idx]=h; g_wlL[idx]=__float2bfloat16(v-__bfloat162float(h));
        return;
    }
    idx-=NWL;
    if(idx<NBM){
        const int n=idx%104,l=idx/104; g_bias[idx]=(n<100)?(l==0?b0[n]:bm[(l-1)*100+n]):0.f;
        return;
    }
    idx-=NBM;
    if(idx<NBL) g_biasL[idx]=(idx<441)?bl[idx]:0.f;
}
__global__ void prepI_k(const float* __restrict__ in){
    const int pix=blockIdx.x*blockDim.x+threadIdx.x; if(pix>=HWSZ) return;
    __nv_bfloat16* ph=g_inH+(size_t)pix*64; __nv_bfloat16* pl=g_inL+(size_t)pix*64;
    #pragma unroll
    for(int c=0;c<64;c++){
        float v=(c<10)?in[(size_t)c*HWSZ+pix]:0.f;
        __nv_bfloat16 h=__float2bfloat16(v); ph[c]=h; pl[c]=__float2bfloat16(v-__bfloat162float(h));
    }
    const uint4 z=make_uint4(0,0,0,0);
    #pragma unroll
    for(int b=0;b<2;b++){
        uint4* qh=(uint4*)(g_actH[b]+(size_t)pix*128+104);
        uint4* ql=(uint4*)(g_actL[b]+(size_t)pix*128+104);
        qh[0]=z; qh[1]=z; qh[2]=z; ql[0]=z; ql[1]=z; ql[2]=z;
    }
}

// ---------------------------------------------------------------------------
// Warp-MMA implicit-GEMM conv: halo-resident A, phased ch-blocks,
// asymmetric N-tiling (wn0: 7 tiles n0-55, wn1: 6 tiles n56-103),
// SMSP-balanced warp map (wm=wid&3, wn=wid>>2). 2 CTAs/SM.
// ---------------------------------------------------------------------------
#define SMEM_MM (1024 + 2*23040 + 2*26624)

template<int CBIN,bool LEAKY>
__global__ __launch_bounds__(256,2)
void convMMA(const __nv_bfloat16* __restrict__ aH,const __nv_bfloat16* __restrict__ aL,
             const __nv_bfloat16* __restrict__ wH,const __nv_bfloat16* __restrict__ wL,
             const float* __restrict__ bias,
             __nv_bfloat16* __restrict__ oH,__nv_bfloat16* __restrict__ oL)
{
    extern __shared__ char dyn[];
    __shared__ float s_bias[104];
    const int tid=threadIdx.x, lane=tid&31, wid=tid>>5;
    const int wm=wid&3, wn=wid>>2;
    const int x0=blockIdx.x*16, y0=blockIdx.y*8;
    char* dynp=(char*)(((uintptr_t)dyn+1023)&~(uintptr_t)1023);
    const unsigned sbase=smem_u32(dynp);
    const unsigned sA=sbase;
    const unsigned sB=sbase+2u*AHALO;
    if(tid<104) s_bias[tid]=bias[tid];

    auto stageA=[&](int cb){
        for(int idx=tid; idx<2880; idx+=256){
            const int seg=idx&7, rowq=idx>>3;
            const int row=rowq%180, hl=rowq/180;
            const int yr=row/18, col=row-yr*18;
            const int gy=y0+yr-1, gx=x0+col-1;
            const bool ok=(unsigned)gy<HH&&(unsigned)gx<WW;
            const __nv_bfloat16* src=(hl?aL:aH)+((size_t)(ok?(gy*WW+gx):0))*(CBIN*64)+cb*64+seg*8;
            cpa16(sA+(unsigned)hl*AHALO+sw128((unsigned)(row*128+seg*16)),src,ok?16:0);
        }
    };
    auto loadB=[&](int off,int cb,int buf){
        const unsigned base=sB+(unsigned)buf*26624u;
        #pragma unroll
        for(int k=0;k<7;k++){
            const int idx=tid+k*256; if(idx>=1664) break;
            const int hl=idx>=832?1:0, rr=idx-hl*832, n=rr>>3, i=rr&7;
            const __nv_bfloat16* src=(hl?wL:wH)+((size_t)(off*CBIN+cb)*104+n)*64+i*8;
            cpa16(base+hl*13312u+sw128((unsigned)(n*128+i*16)),src,16);
        }
    };

    float C[7][2][4];
    #pragma unroll
    for(int t=0;t<7;t++)
        #pragma unroll
        for(int mt=0;mt<2;mt++)
            #pragma unroll
            for(int q=0;q<4;q++) C[t][mt][q]=0.f;

    const int brow0=(wm*2+0+1)*18+(lane&15)+1;
    const int brow1=(wm*2+1+1)*18+(lane&15)+1;
    const unsigned klane=((lane&16)?16u:0u);
    const int nbase=wn?56:0;

    for(int cb=0;cb<CBIN;cb++){
        if(cb>0) __syncthreads();            // protect A halo reuse
        stageA(cb);
        loadB(0,cb,0);
        cpa_commit();
        for(int s=0;s<9;s++){
            cpa_wait0();
            __syncthreads();
            if(s<8){ loadB(s+1,cb,(s+1)&1); cpa_commit(); }
            const int rdel=(s/3-1)*18+(s%3-1);
            const unsigned bB=sB+(unsigned)(s&1)*26624u;
            if(wn==0){
                if(CBIN==1)    computeStage<1,7>(sA,bB,13312u,rdel,brow0,brow1,klane,nbase,lane,C);
                else if(cb==0) computeStage<4,7>(sA,bB,13312u,rdel,brow0,brow1,klane,nbase,lane,C);
                else           computeStage<3,7>(sA,bB,13312u,rdel,brow0,brow1,klane,nbase,lane,C);
            }else{
                if(CBIN==1)    computeStage<1,6>(sA,bB,13312u,rdel,brow0,brow1,klane,nbase,lane,C);
                else if(cb==0) computeStage<4,6>(sA,bB,13312u,rdel,brow0,brow1,klane,nbase,lane,C);
                else           computeStage<3,6>(sA,bB,13312u,rdel,brow0,brow1,klane,nbase,lane,C);
            }
        }
    }
    __syncthreads();

    // ---- epilogue: stage in smem, coalesced uint4 stores ----
    char* s_hi=dynp;
    char* s_lo=dynp+26624;
    const int NTw=wn?6:7;
    for(int t=0;t<NTw;t++){
        const int n0=nbase+t*8+2*(lane&3);
        #pragma unroll
        for(int mt=0;mt<2;mt++){
            const int mr=wm*32+mt*16+(lane>>2);
            #pragma unroll
            for(int h=0;h<2;h++){
                const int m=mr+h*8;
                float v0=C[t][mt][2*h+0]+s_bias[n0];
                float v1=C[t][mt][2*h+1]+s_bias[n0+1];
                if(LEAKY){ v0=(v0>0.f)?v0:0.01f*v0; v1=(v1>0.f)?v1:0.01f*v1; }
                __nv_bfloat16 h0,h1;
                const uint32_t hp=pack_bf16(v0,v1,h0,h1);
                const uint32_t lp=pack_bf16(v0-__bfloat162float(h0),v1-__bfloat162float(h1),h0,h1);
                *(uint32_t*)(s_hi + m*208 + n0*2)=hp;
                *(uint32_t*)(s_lo + m*208 + n0*2)=lp;
            }
        }
    }
    __syncthreads();
    for(int idx=tid; idx<3328; idx+=256){
        const int buf=idx>=1664; const int r=idx-buf*1664;
        const int px=r/13, q=r-px*13;
        const uint4 val=*(uint4*)((buf?s_lo:s_hi) + px*208 + q*16);
        const int pix=(y0+(px>>4))*WW+x0+(px&15);
        *(uint4*)((buf?oL:oH)+(size_t)pix*128+q*8)=val;
    }
}

// ---------------------------------------------------------------------------
// conv_last as MMA: N=112 per z-pass (z=0..3), planar fp32 W output.
// ---------------------------------------------------------------------------
#define SMEM_CL (1024 + 2*23040 + 2*28672)
__global__ __launch_bounds__(256,2)
void convlastMMA(const __nv_bfloat16* __restrict__ aH,const __nv_bfloat16* __restrict__ aL)
{
    extern __shared__ char dyn[];
    __shared__ float s_bias[112];
    const int tid=threadIdx.x, lane=tid&31, wid=tid>>5;
    const int wm=wid&3, wn=wid>>2;
    const int x0=blockIdx.x*16, y0=blockIdx.y*8, z=blockIdx.z;
    char* dynp=(char*)(((uintptr_t)dyn+1023)&~(uintptr_t)1023);
    const unsigned sbase=smem_u32(dynp);
    const unsigned sA=sbase;
    const unsigned sB=sbase+2u*AHALO;
    if(tid<112) s_bias[tid]=g_biasL[z*112+tid];

    auto stageA=[&](int cb){
        for(int idx=tid; idx<2880; idx+=256){
            const int seg=idx&7, rowq=idx>>3;
            const int row=rowq%180, hl=rowq/180;
            const int yr=row/18, col=row-yr*18;
            const int gy=y0+yr-1, gx=x0+col-1;
            const bool ok=(unsigned)gy<HH&&(unsigned)gx<WW;
            const __nv_bfloat16* src=(hl?aL:aH)+((size_t)(ok?(gy*WW+gx):0))*128+cb*64+seg*8;
            cpa16(sA+(unsigned)hl*AHALO+sw128((unsigned)(row*128+seg*16)),src,ok?16:0);
        }
    };
    auto loadB=[&](int off,int cb,int buf){
        const unsigned base=sB+(unsigned)buf*28672u;
        #pragma unroll
        for(int k=0;k<7;k++){
            const int idx=tid+k*256;
            const int hl=idx>=896?1:0, rr=idx-hl*896, n=rr>>3, i=rr&7;
            const __nv_bfloat16* src=(hl?g_wlL:g_wlH)+((size_t)(off*2+cb)*448+z*112+n)*64+i*8;
            cpa16(base+hl*14336u+sw128((unsigned)(n*128+i*16)),src,16);
        }
    };

    float C[7][2][4];
    #pragma unroll
    for(int t=0;t<7;t++)
        #pragma unroll
        for(int mt=0;mt<2;mt++)
            #pragma unroll
            for(int q=0;q<4;q++) C[t][mt][q]=0.f;

    const int brow0=(wm*2+0+1)*18+(lane&15)+1;
    const int brow1=(wm*2+1+1)*18+(lane&15)+1;
    const unsigned klane=((lane&16)?16u:0u);
    const int nbase=wn*56;

    for(int cb=0;cb<2;cb++){
        if(cb>0) __syncthreads();
        stageA(cb);
        loadB(0,cb,0);
        cpa_commit();
        for(int s=0;s<9;s++){
            cpa_wait0();
            __syncthreads();
            if(s<8){ loadB(s+1,cb,(s+1)&1); cpa_commit(); }
            const int rdel=(s/3-1)*18+(s%3-1);
            const unsigned bB=sB+(unsigned)(s&1)*28672u;
            if(cb==0) computeStage<4,7>(sA,bB,14336u,rdel,brow0,brow1,klane,nbase,lane,C);
            else      computeStage<3,7>(sA,bB,14336u,rdel,brow0,brow1,klane,nbase,lane,C);
        }
    }
    __syncthreads();

    // ---- epilogue: s_W[112 oc][128 px] fp32, planar coalesced stores ----
    float* s_W=(float*)dynp;
    #pragma unroll
    for(int t=0;t<7;t++){
        const int n0=wn*56+t*8+2*(lane&3);
        #pragma unroll
        for(int mt=0;mt<2;mt++){
            const int mr=wm*32+mt*16+(lane>>2);
            #pragma unroll
            for(int h=0;h<2;h++){
                const int m=mr+h*8;
                s_W[n0*128+m]    =C[t][mt][2*h+0]+s_bias[n0];
                s_W[(n0+1)*128+m]=C[t][mt][2*h+1]+s_bias[n0+1];
            }
        }
    }
    __syncthreads();
    for(int idx=tid; idx<112*32; idx+=256){
        const int oc=idx>>5, c=idx&31;
        const int px0=c*4;
        const uint4 val=*(uint4*)(s_W+oc*128+px0);
        const int pix=(y0+(px0>>4))*WW+x0+(px0&15);
        *(uint4*)(g_W+(size_t)(z*112+oc)*HWSZ+pix)=val;
    }
}

// ---------------------------------------------------------------------------
// Kernel regression
// ---------------------------------------------------------------------------
__global__ __launch_bounds__(256)
void regress_k(const float* __restrict__ rgb, float* __restrict__ out)
{
    __shared__ float s_rgb[3][28][52];
    const int tid=threadIdx.x;
    const int tx=tid&31, ty=tid>>5;
    const int x0=blockIdx.x*32, y0=blockIdx.y*8;
    for(int idx=tid; idx<3*28*52; idx+=256){
        const int cl=idx%52, t1=idx/52;
        const int rr=t1%28, cc=t1/28;
        const int gy=y0+rr-10, gx=x0+cl-10;
        s_rgb[cc][rr][cl]=((unsigned)gy<HH&&(unsigned)gx<WW)?rgb[(size_t)cc*HWSZ+gy*WW+gx]:0.f;
    }
    __syncthreads();
    const int pix=(y0+ty)*WW+x0+tx;
    float sr=0.f,sg=0.f,sb=0.f,ss=0.f;
    const float* wp=g_W+pix;
    int k=0;
    for(int dy=0;dy<21;dy++){
        const float* r0=&s_rgb[0][ty+dy][tx];
        const float* r1=&s_rgb[1][ty+dy][tx];
        const float* r2=&s_rgb[2][ty+dy][tx];
        #pragma unroll
        for(int dx=0;dx<21;dx++){
            const float wk=wp[(size_t)k*HWSZ];
            sr=fmaf(wk,r0[dx],sr); sg=fmaf(wk,r1[dx],sg); sb=fmaf(wk,r2[dx],sb); ss+=wk;
            k++;
        }
    }
    const float inv=1.f/(ss+1e-6f);
    out[pix]=sr*inv; out[(size_t)HWSZ+pix]=sg*inv; out[(size_t)2*HWSZ+pix]=sb*inv;
}

// ---------------------------------------------------------------------------
extern "C" void kernel_launch(void* const* d_in,const int* in_sizes,int n_in,void* d_out,int out_size)
{
    const float* input=(const float*)d_in[0];
    const float* w0=(const float*)d_in[2];
    const float* b0=(const float*)d_in[3];
    const float* w_mid=(const float*)d_in[4];
    const float* b_mid=(const float*)d_in[5];
    const float* w_last=(const float*)d_in[6];
    const float* b_last=(const float*)d_in[7];
    float* out=(float*)d_out;

    cudaFuncSetAttribute(convMMA<1,false>,cudaFuncAttributeMaxDynamicSharedMemorySize,SMEM_MM);
    cudaFuncSetAttribute(convMMA<2,true>,cudaFuncAttributeMaxDynamicSharedMemorySize,SMEM_MM);
    cudaFuncSetAttribute(convlastMMA,cudaFuncAttributeMaxDynamicSharedMemorySize,SMEM_CL);

    __nv_bfloat16 *aH,*aL,*iH,*iL,*wmH,*wmL,*w0H,*w0L; float *bias;
    cudaGetSymbolAddress((void**)&aH,g_actH); cudaGetSymbolAddress((void**)&aL,g_actL);
    cudaGetSymbolAddress((void**)&iH,g_inH);  cudaGetSymbolAddress((void**)&iL,g_inL);
    cudaGetSymbolAddress((void**)&wmH,g_wmH); cudaGetSymbolAddress((void**)&wmL,g_wmL);
    cudaGetSymbolAddress((void**)&w0H,g_w0H); cudaGetSymbolAddress((void**)&w0L,g_w0L);
    cudaGetSymbolAddress((void**)&bias,g_bias);
    const size_t ACT=(size_t)HWSZ*128;
    const size_t WL=(size_t)9*2*104*64;

    const int NPREP=NW0+NWM+NWL+NBM+NBL;
    prepW_k<<<(NPREP+255)/256,256>>>(w0,w_mid,w_last,b0,b_mid,b_last);
    prepI_k<<<HWSZ/256,256>>>(input);

    const dim3 gmm(WW/16,HH/8);
    convMMA<1,false><<<gmm,256,SMEM_MM>>>(iH,iL,w0H,w0L,bias,aH,aL);
    for(int l=0;l<23;l++){
        const int rd=l&1, wr=1-rd;
        convMMA<2,true><<<gmm,256,SMEM_MM>>>(aH+rd*ACT,aL+rd*ACT,wmH+(size_t)l*WL,wmL+(size_t)l*WL,
            bias+(l+1)*104,aH+wr*ACT,aL+wr*ACT);
    }
    convlastMMA<<<dim3(WW/16,HH/8,4),256,SMEM_CL>>>(aH+ACT,aL+ACT);

    regress_k<<<dim3(WW/32,HH/8),256>>>(input,out);
}